// round 1
// baseline (speedup 1.0000x reference)
#include <cuda_runtime.h>
#include <math.h>

#define NNODES 50000
#define NEDGES 800000
#define NETOT  (NEDGES + NNODES)
#define NGRAPH 64

// ---------------- scratch (device globals; no allocation allowed) ----------------
__device__ float g_h[NNODES * 256];      // per-layer projected features [N, H*C]
__device__ float g_als[NNODES * 4];      // src attention coefficient per head
__device__ float g_ald[NNODES * 4];      // dst attention coefficient per head
__device__ float g_x1[NNODES * 64];
__device__ float g_x2[NNODES * 64];
__device__ int   g_deg[NNODES];
__device__ int   g_rowptr[NNODES + 1];
__device__ int   g_cursor[NNODES];
__device__ int   g_csr[NETOT];           // src index per in-edge, grouped by dst

// ---------------- helpers ----------------
__device__ __forceinline__ float warp_sum(float v) {
  #pragma unroll
  for (int o = 16; o; o >>= 1) v += __shfl_xor_sync(0xffffffffu, v, o);
  return v;
}
__device__ __forceinline__ float warp_max(float v) {
  #pragma unroll
  for (int o = 16; o; o >>= 1) v = fmaxf(v, __shfl_xor_sync(0xffffffffu, v, o));
  return v;
}
__device__ __forceinline__ float lrelu(float v) { return v > 0.f ? v : 0.2f * v; }

// ---------------- CSR build ----------------
__global__ void k_zero_counts() {
  int i = blockIdx.x * blockDim.x + threadIdx.x;
  if (i < NNODES) { g_deg[i] = 0; g_cursor[i] = 0; }
}

__global__ void k_count(const int* __restrict__ ei) {
  int i = blockIdx.x * blockDim.x + threadIdx.x;
  if (i >= NETOT) return;
  int d = (i < NEDGES) ? ei[NEDGES + i] : (i - NEDGES);   // self-loops appended
  atomicAdd(&g_deg[d], 1);
}

__global__ void k_scan() {   // single-block exclusive scan of g_deg -> g_rowptr
  __shared__ int tmp[1024];
  __shared__ int s_off;
  int tid = threadIdx.x;
  if (tid == 0) s_off = 0;
  __syncthreads();
  for (int base = 0; base < NNODES; base += 1024) {
    int i = base + tid;
    int v = (i < NNODES) ? g_deg[i] : 0;
    tmp[tid] = v;
    __syncthreads();
    for (int d = 1; d < 1024; d <<= 1) {
      int t = (tid >= d) ? tmp[tid - d] : 0;
      __syncthreads();
      tmp[tid] += t;
      __syncthreads();
    }
    int off = s_off;
    if (i < NNODES) g_rowptr[i] = off + tmp[tid] - v;
    __syncthreads();
    if (tid == 0) s_off = off + tmp[1023];
    __syncthreads();
  }
  if (tid == 0) g_rowptr[NNODES] = s_off;
}

__global__ void k_fill(const int* __restrict__ ei) {
  int i = blockIdx.x * blockDim.x + threadIdx.x;
  if (i >= NETOT) return;
  int s, d;
  if (i < NEDGES) { s = ei[i]; d = ei[NEDGES + i]; }
  else            { s = i - NEDGES; d = s; }
  int pos = atomicAdd(&g_cursor[d], 1);
  g_csr[g_rowptr[d] + pos] = s;
}

// ---------------- GEMM: h = X[N,K] @ W[K,256] -> g_h ----------------
// 64x64 output tile per block, 256 threads, 4x4 micro-tile per thread.
template<int K>
__global__ void k_gemm(const float* __restrict__ Xext, int src_sel,
                       const float* __restrict__ W) {
  const float* __restrict__ X = (src_sel == 1) ? g_x1 : (src_sel == 2) ? g_x2 : Xext;
  __shared__ float Xs[64][33];
  __shared__ float Ws[32][65];
  int tid = threadIdx.x;
  int tx = tid & 15, ty = tid >> 4;
  int row0 = blockIdx.y * 64, col0 = blockIdx.x * 64;
  float acc[4][4];
  #pragma unroll
  for (int i = 0; i < 4; i++)
    #pragma unroll
    for (int j = 0; j < 4; j++) acc[i][j] = 0.f;
  for (int kk = 0; kk < K; kk += 32) {
    for (int t = tid; t < 64 * 32; t += 256) {
      int r = t >> 5, c = t & 31;
      int row = row0 + r;
      Xs[r][c] = (row < NNODES) ? X[(size_t)row * K + kk + c] : 0.f;
    }
    for (int t = tid; t < 32 * 64; t += 256) {
      int r = t >> 6, c = t & 63;
      Ws[r][c] = W[(kk + r) * 256 + col0 + c];
    }
    __syncthreads();
    #pragma unroll
    for (int k = 0; k < 32; k++) {
      float a[4], b[4];
      #pragma unroll
      for (int i = 0; i < 4; i++) a[i] = Xs[ty * 4 + i][k];
      #pragma unroll
      for (int j = 0; j < 4; j++) b[j] = Ws[k][tx * 4 + j];
      #pragma unroll
      for (int i = 0; i < 4; i++)
        #pragma unroll
        for (int j = 0; j < 4; j++) acc[i][j] = fmaf(a[i], b[j], acc[i][j]);
    }
    __syncthreads();
  }
  #pragma unroll
  for (int i = 0; i < 4; i++) {
    int row = row0 + ty * 4 + i;
    if (row < NNODES) {
      #pragma unroll
      for (int j = 0; j < 4; j++)
        g_h[(size_t)row * 256 + col0 + tx * 4 + j] = acc[i][j];
    }
  }
}

// ---------------- attention coefficients: al_s/al_d[n,h] = <h[n,h,:], a[h,:]> ----------------
__global__ void k_attn(const float* __restrict__ a_s, const float* __restrict__ a_d) {
  int w = (blockIdx.x * blockDim.x + threadIdx.x) >> 5;
  int lane = threadIdx.x & 31;
  if (w >= NNODES) return;
  const float* hp = g_h + (size_t)w * 256;
  float ss[8], dd[8];
  #pragma unroll
  for (int k = 0; k < 8; k++) {
    int j = lane + 32 * k;                 // flat (head,channel) index; head = k>>1
    float v = hp[j];
    ss[k] = v * a_s[j];
    dd[k] = v * a_d[j];
  }
  #pragma unroll
  for (int hd = 0; hd < 4; hd++) {
    float s = warp_sum(ss[2 * hd] + ss[2 * hd + 1]);
    float d = warp_sum(dd[2 * hd] + dd[2 * hd + 1]);
    if (lane == 0) { g_als[w * 4 + hd] = s; g_ald[w * 4 + hd] = d; }
  }
}

// ---------------- GAT aggregate: softmax over in-edges + weighted sum, head-mean + bias ----------------
// one warp per dst node; channels c = lane + 32k (k=0..7), head(c) = k>>1
__global__ void k_aggregate(const float* __restrict__ bias, float* __restrict__ xout_ext,
                            int dst_sel, int relu_flag) {
  float* __restrict__ xout = (dst_sel == 1) ? g_x1 : (dst_sel == 2) ? g_x2 : xout_ext;
  int w = (blockIdx.x * blockDim.x + threadIdx.x) >> 5;
  int lane = threadIdx.x & 31;
  if (w >= NNODES) return;
  int beg = g_rowptr[w], end = g_rowptr[w + 1];
  const float4* __restrict__ als4 = (const float4*)g_als;
  float4 ad = ((const float4*)g_ald)[w];

  // pass 1: per-head max (leaky-relu'd logits)
  float m0 = -1e30f, m1 = -1e30f, m2 = -1e30f, m3 = -1e30f;
  for (int e = beg + lane; e < end; e += 32) {
    float4 as = als4[g_csr[e]];
    m0 = fmaxf(m0, lrelu(as.x + ad.x));
    m1 = fmaxf(m1, lrelu(as.y + ad.y));
    m2 = fmaxf(m2, lrelu(as.z + ad.z));
    m3 = fmaxf(m3, lrelu(as.w + ad.w));
  }
  m0 = warp_max(m0); m1 = warp_max(m1); m2 = warp_max(m2); m3 = warp_max(m3);

  // pass 2: per-head exp-sum
  float s0 = 0.f, s1 = 0.f, s2 = 0.f, s3 = 0.f;
  for (int e = beg + lane; e < end; e += 32) {
    float4 as = als4[g_csr[e]];
    s0 += __expf(lrelu(as.x + ad.x) - m0);
    s1 += __expf(lrelu(as.y + ad.y) - m1);
    s2 += __expf(lrelu(as.z + ad.z) - m2);
    s3 += __expf(lrelu(as.w + ad.w) - m3);
  }
  s0 = warp_sum(s0); s1 = warp_sum(s1); s2 = warp_sum(s2); s3 = warp_sum(s3);
  float i0 = 1.f / s0, i1 = 1.f / s1, i2 = 1.f / s2, i3 = 1.f / s3;

  // pass 3: weighted accumulate, coalesced 1KB gather per edge
  float acc[8] = {0, 0, 0, 0, 0, 0, 0, 0};
  for (int e = beg; e < end; e++) {
    int s = g_csr[e];                      // uniform per warp -> broadcast
    float4 as = als4[s];
    float al[4];
    al[0] = __expf(lrelu(as.x + ad.x) - m0) * i0;
    al[1] = __expf(lrelu(as.y + ad.y) - m1) * i1;
    al[2] = __expf(lrelu(as.z + ad.z) - m2) * i2;
    al[3] = __expf(lrelu(as.w + ad.w) - m3) * i3;
    const float* hp = g_h + (size_t)s * 256;
    #pragma unroll
    for (int k = 0; k < 8; k++)
      acc[k] = fmaf(al[k >> 1], hp[lane + 32 * k], acc[k]);
  }
  // head-mean (channels lane and lane+32) + bias (+relu)
  float c0 = (acc[0] + acc[2] + acc[4] + acc[6]) * 0.25f + bias[lane];
  float c1 = (acc[1] + acc[3] + acc[5] + acc[7]) * 0.25f + bias[lane + 32];
  if (relu_flag) { c0 = fmaxf(c0, 0.f); c1 = fmaxf(c1, 0.f); }
  xout[(size_t)w * 64 + lane] = c0;
  xout[(size_t)w * 64 + 32 + lane] = c1;
}

// ---------------- per-node MLP heads (anomaly/risk sigmoid, resource 5-dim) ----------------
__global__ void k_heads(const float* __restrict__ emb,
                        const float* __restrict__ aw1, const float* __restrict__ ab1,
                        const float* __restrict__ aw2, const float* __restrict__ ab2,
                        const float* __restrict__ rw1, const float* __restrict__ rb1,
                        const float* __restrict__ rw2, const float* __restrict__ rb2,
                        const float* __restrict__ cw1, const float* __restrict__ cb1,
                        const float* __restrict__ cw2, const float* __restrict__ cb2,
                        float* __restrict__ anomaly, float* __restrict__ risk,
                        float* __restrict__ resource) {
  __shared__ float s_a1[2048], s_r1[2048], s_c1[2048];
  __shared__ float s_a2[32], s_r2[32], s_c2[160];
  __shared__ float s_ab1[32], s_rb1[32], s_cb1[32];
  __shared__ float s_ab2, s_rb2, s_cb2[5];
  int tid = threadIdx.x;
  for (int t = tid; t < 2048; t += blockDim.x) { s_a1[t] = aw1[t]; s_r1[t] = rw1[t]; s_c1[t] = cw1[t]; }
  for (int t = tid; t < 160; t += blockDim.x) s_c2[t] = cw2[t];
  if (tid < 32) { s_a2[tid] = aw2[tid]; s_r2[tid] = rw2[tid];
                  s_ab1[tid] = ab1[tid]; s_rb1[tid] = rb1[tid]; s_cb1[tid] = cb1[tid]; }
  if (tid == 0) { s_ab2 = ab2[0]; s_rb2 = rb2[0]; }
  if (tid < 5) s_cb2[tid] = cb2[tid];
  __syncthreads();
  int w = (blockIdx.x * blockDim.x + tid) >> 5;
  int lane = tid & 31;
  if (w >= NNODES) return;
  float e0 = emb[(size_t)w * 64 + lane];
  float e1 = emb[(size_t)w * 64 + 32 + lane];
  float ha = s_ab1[lane], hr = s_rb1[lane], hc = s_cb1[lane];
  #pragma unroll
  for (int c = 0; c < 32; c++) {
    float x = __shfl_sync(0xffffffffu, e0, c);
    ha = fmaf(x, s_a1[c * 32 + lane], ha);
    hr = fmaf(x, s_r1[c * 32 + lane], hr);
    hc = fmaf(x, s_c1[c * 32 + lane], hc);
  }
  #pragma unroll
  for (int c = 0; c < 32; c++) {
    float x = __shfl_sync(0xffffffffu, e1, c);
    ha = fmaf(x, s_a1[(c + 32) * 32 + lane], ha);
    hr = fmaf(x, s_r1[(c + 32) * 32 + lane], hr);
    hc = fmaf(x, s_c1[(c + 32) * 32 + lane], hc);
  }
  ha = fmaxf(ha, 0.f); hr = fmaxf(hr, 0.f); hc = fmaxf(hc, 0.f);
  float pa = warp_sum(ha * s_a2[lane]);
  float pr = warp_sum(hr * s_r2[lane]);
  if (lane == 0) {
    anomaly[w] = 1.f / (1.f + __expf(-(pa + s_ab2)));
    risk[w]    = 1.f / (1.f + __expf(-(pr + s_rb2)));
  }
  #pragma unroll
  for (int o = 0; o < 5; o++) {
    float p = warp_sum(hc * s_c2[lane * 5 + o]);
    if (lane == 0) resource[(size_t)w * 5 + o] = p + s_cb2[o];
  }
}

// ---------------- global mean pool (batch is sorted) + graph MLP ----------------
__global__ void k_pool(const float* __restrict__ emb, const int* __restrict__ batch,
                       const float* __restrict__ gw1, const float* __restrict__ gb1,
                       const float* __restrict__ gw2, const float* __restrict__ gb2,
                       float* __restrict__ glog) {
  __shared__ float part[256];
  __shared__ float pooled[64];
  __shared__ float hidden[32];
  __shared__ int s_lo, s_hi;
  int g = blockIdx.x;
  int tid = threadIdx.x;
  if (tid == 0) {
    int lo = 0, hi = NNODES;
    while (lo < hi) { int mid = (lo + hi) >> 1; if (batch[mid] < g) lo = mid + 1; else hi = mid; }
    int lo2 = lo, hi2 = NNODES;
    while (lo2 < hi2) { int mid = (lo2 + hi2) >> 1; if (batch[mid] <= g) lo2 = mid + 1; else hi2 = mid; }
    s_lo = lo; s_hi = lo2;
  }
  __syncthreads();
  int lo = s_lo, hi = s_hi;
  int c = tid & 63, sub = tid >> 6;
  float acc = 0.f;
  for (int i = lo + sub; i < hi; i += 4) acc += emb[(size_t)i * 64 + c];
  part[tid] = acc;
  __syncthreads();
  if (tid < 64) {
    float cnt = fmaxf((float)(hi - lo), 1.f);
    pooled[tid] = (part[tid] + part[tid + 64] + part[tid + 128] + part[tid + 192]) / cnt;
  }
  __syncthreads();
  if (tid < 32) {
    float h = gb1[tid];
    #pragma unroll
    for (int cc = 0; cc < 64; cc++) h = fmaf(pooled[cc], gw1[cc * 32 + tid], h);
    hidden[tid] = fmaxf(h, 0.f);
  }
  __syncthreads();
  if (tid < 4) {
    float o = gb2[tid];
    #pragma unroll
    for (int j = 0; j < 32; j++) o = fmaf(hidden[j], gw2[j * 4 + tid], o);
    glog[g * 4 + tid] = o;
  }
}

// ---------------- launch ----------------
extern "C" void kernel_launch(void* const* d_in, const int* in_sizes, int n_in,
                              void* d_out, int out_size) {
  const float* x     = (const float*)d_in[0];
  const int*   ei    = (const int*)d_in[1];
  const int*   batch = (const int*)d_in[2];
  const float* W1  = (const float*)d_in[3];
  const float* as1 = (const float*)d_in[4];
  const float* ad1 = (const float*)d_in[5];
  const float* b1  = (const float*)d_in[6];
  const float* W2  = (const float*)d_in[7];
  const float* as2 = (const float*)d_in[8];
  const float* ad2 = (const float*)d_in[9];
  const float* b2  = (const float*)d_in[10];
  const float* W3  = (const float*)d_in[11];
  const float* as3 = (const float*)d_in[12];
  const float* ad3 = (const float*)d_in[13];
  const float* b3  = (const float*)d_in[14];
  const float* aw1 = (const float*)d_in[15];
  const float* ab1 = (const float*)d_in[16];
  const float* aw2 = (const float*)d_in[17];
  const float* ab2 = (const float*)d_in[18];
  const float* rw1 = (const float*)d_in[19];
  const float* rb1 = (const float*)d_in[20];
  const float* rw2 = (const float*)d_in[21];
  const float* rb2 = (const float*)d_in[22];
  const float* cw1 = (const float*)d_in[23];
  const float* cb1 = (const float*)d_in[24];
  const float* cw2 = (const float*)d_in[25];
  const float* cb2 = (const float*)d_in[26];
  const float* gw1 = (const float*)d_in[27];
  const float* gb1 = (const float*)d_in[28];
  const float* gw2 = (const float*)d_in[29];
  const float* gb2 = (const float*)d_in[30];

  float* out      = (float*)d_out;
  float* emb      = out;                               // [N,64]
  float* anomaly  = emb + (size_t)NNODES * 64;         // [N]
  float* risk     = anomaly + NNODES;                  // [N]
  float* resource = risk + NNODES;                     // [N,5]
  float* glog     = resource + (size_t)NNODES * 5;     // [G,4]

  // CSR build (dst-grouped, self-loops included)
  k_zero_counts<<<(NNODES + 255) / 256, 256>>>();
  k_count<<<(NETOT + 255) / 256, 256>>>(ei);
  k_scan<<<1, 1024>>>();
  k_fill<<<(NETOT + 255) / 256, 256>>>(ei);

  dim3 gemm_grid(4, (NNODES + 63) / 64);
  int warp_blocks = (NNODES * 32 + 255) / 256;

  // Layer 1
  k_gemm<128><<<gemm_grid, 256>>>(x, 0, W1);
  k_attn<<<warp_blocks, 256>>>(as1, ad1);
  k_aggregate<<<warp_blocks, 256>>>(b1, nullptr, 1, 1);   // -> g_x1, relu
  // Layer 2
  k_gemm<64><<<gemm_grid, 256>>>(nullptr, 1, W2);
  k_attn<<<warp_blocks, 256>>>(as2, ad2);
  k_aggregate<<<warp_blocks, 256>>>(b2, nullptr, 2, 1);   // -> g_x2, relu
  // Layer 3
  k_gemm<64><<<gemm_grid, 256>>>(nullptr, 2, W3);
  k_attn<<<warp_blocks, 256>>>(as3, ad3);
  k_aggregate<<<warp_blocks, 256>>>(b3, emb, 0, 0);       // -> emb (d_out), no relu

  // Heads + pooling
  k_heads<<<(NNODES * 32 + 511) / 512, 512>>>(emb, aw1, ab1, aw2, ab2,
                                              rw1, rb1, rw2, rb2,
                                              cw1, cb1, cw2, cb2,
                                              anomaly, risk, resource);
  k_pool<<<NGRAPH, 256>>>(emb, batch, gw1, gb1, gw2, gb2, glog);
}

// round 2
// speedup vs baseline: 2.2306x; 2.2306x over previous
#include <cuda_runtime.h>
#include <cuda_fp16.h>
#include <math.h>

#define NNODES 50000
#define NEDGES 800000
#define NETOT  (NEDGES + NNODES)
#define NGRAPH 64
#define NBLK_SCAN ((NNODES + 255) / 256)   // 196

// ---------------- scratch (device globals; no allocation allowed) ----------------
__device__ __half g_hh[NNODES * 256];    // projected features, fp16 [N, H*C]
__device__ float g_als[NNODES * 4];      // src attention logit per head
__device__ float g_ald[NNODES * 4];      // dst attention logit per head
__device__ float g_x1[NNODES * 64];
__device__ float g_x2[NNODES * 64];
__device__ int   g_deg[NNODES];
__device__ int   g_rowptr[NNODES + 1];
__device__ int   g_cursor[NNODES];
__device__ int   g_bsum[256];
__device__ int   g_csr[NETOT];           // src index per in-edge, grouped by dst

// ---------------- helpers ----------------
__device__ __forceinline__ float warp_sum(float v) {
  #pragma unroll
  for (int o = 16; o; o >>= 1) v += __shfl_xor_sync(0xffffffffu, v, o);
  return v;
}
__device__ __forceinline__ float warp_max(float v) {
  #pragma unroll
  for (int o = 16; o; o >>= 1) v = fmaxf(v, __shfl_xor_sync(0xffffffffu, v, o));
  return v;
}
__device__ __forceinline__ float lrelu(float v) { return v > 0.f ? v : 0.2f * v; }

typedef unsigned long long ull;
__device__ __forceinline__ ull pack2(float x, float y) {
  ull r; asm("mov.b64 %0,{%1,%2};" : "=l"(r) : "f"(x), "f"(y)); return r;
}
__device__ __forceinline__ void ffma2(ull& d, ull a, ull b) {
  asm("fma.rn.f32x2 %0,%1,%2,%0;" : "+l"(d) : "l"(a), "l"(b));
}
__device__ __forceinline__ float2 unpack2(ull v) {
  float2 f; asm("mov.b64 {%0,%1},%2;" : "=f"(f.x), "=f"(f.y) : "l"(v)); return f;
}

// ---------------- CSR build ----------------
__global__ void k_zero_counts() {
  int i = blockIdx.x * blockDim.x + threadIdx.x;
  if (i < NNODES) { g_deg[i] = 0; g_cursor[i] = 0; }
}

__global__ void k_count(const int* __restrict__ ei) {
  int i = blockIdx.x * blockDim.x + threadIdx.x;
  if (i >= NETOT) return;
  int d = (i < NEDGES) ? ei[NEDGES + i] : (i - NEDGES);   // self-loops appended
  atomicAdd(&g_deg[d], 1);
}

// two-level scan: per-block inclusive scan -> block sums -> offset add
__global__ void k_scan1() {
  __shared__ int tmp[256];
  int tid = threadIdx.x;
  int i = blockIdx.x * 256 + tid;
  int v = (i < NNODES) ? g_deg[i] : 0;
  tmp[tid] = v;
  __syncthreads();
  #pragma unroll
  for (int d = 1; d < 256; d <<= 1) {
    int t = (tid >= d) ? tmp[tid - d] : 0;
    __syncthreads();
    tmp[tid] += t;
    __syncthreads();
  }
  if (i < NNODES) g_rowptr[i] = tmp[tid] - v;   // exclusive within block
  if (tid == 255) g_bsum[blockIdx.x] = tmp[255];
}

__global__ void k_scan2() {   // 1 block, scan 196 block sums (exclusive)
  __shared__ int tmp[256];
  int tid = threadIdx.x;
  int v = (tid < NBLK_SCAN) ? g_bsum[tid] : 0;
  tmp[tid] = v;
  __syncthreads();
  #pragma unroll
  for (int d = 1; d < 256; d <<= 1) {
    int t = (tid >= d) ? tmp[tid - d] : 0;
    __syncthreads();
    tmp[tid] += t;
    __syncthreads();
  }
  g_bsum[tid] = tmp[tid] - v;
}

__global__ void k_scan3() {
  int i = blockIdx.x * blockDim.x + threadIdx.x;
  if (i < NNODES) g_rowptr[i] += g_bsum[i >> 8];
  if (i == 0) g_rowptr[NNODES] = NETOT;
}

__global__ void k_fill(const int* __restrict__ ei) {
  int i = blockIdx.x * blockDim.x + threadIdx.x;
  if (i >= NETOT) return;
  int s, d;
  if (i < NEDGES) { s = ei[i]; d = ei[NEDGES + i]; }
  else            { s = i - NEDGES; d = s; }
  int pos = atomicAdd(&g_cursor[d], 1);
  g_csr[g_rowptr[d] + pos] = s;
}

// ---------------- fused GEMM + attention-logit epilogue ----------------
// h = X[N,K] @ W[K,256]; tile 128 rows x 64 cols (one head per col-tile).
// 256 threads, micro-tile 8x4, packed fp32x2 FFMA along the row dimension.
// Writes g_hh (fp16) and per-node per-head logits g_als/g_ald.
template<int K>
__global__ void __launch_bounds__(256) k_gemm_fused(
    const float* __restrict__ Xext, int src_sel, const float* __restrict__ W,
    const float* __restrict__ a_s, const float* __restrict__ a_d) {
  const float* __restrict__ X = (src_sel == 1) ? g_x1 : (src_sel == 2) ? g_x2 : Xext;
  __shared__ float Xs[32][132];     // [k][row], 132*4 bytes row stride (16B aligned)
  __shared__ float Ws[32][68];      // [k][col]
  __shared__ float s_as[64], s_ad[64];
  __shared__ float red_s[128][17], red_d[128][17];

  int tid = threadIdx.x;
  int tx = tid & 15, ty = tid >> 4;
  int hd = blockIdx.x;              // head index == column tile
  int col0 = hd * 64;
  int row0 = blockIdx.y * 128;

  if (tid < 64) { s_as[tid] = a_s[col0 + tid]; s_ad[tid] = a_d[col0 + tid]; }

  ull acc[4][4];
  #pragma unroll
  for (int i = 0; i < 4; i++)
    #pragma unroll
    for (int j = 0; j < 4; j++) acc[i][j] = 0ull;

  for (int kk = 0; kk < K; kk += 32) {
    // load X tile transposed: Xs[k][row]
    #pragma unroll
    for (int it = 0; it < 4; it++) {
      int f = tid + it * 256;                 // 1024 float4 slots
      int row = f >> 3, k4 = f & 7;
      float4 v = make_float4(0.f, 0.f, 0.f, 0.f);
      if (row0 + row < NNODES)
        v = *(const float4*)&X[(size_t)(row0 + row) * K + kk + k4 * 4];
      Xs[k4 * 4 + 0][row] = v.x;
      Xs[k4 * 4 + 1][row] = v.y;
      Xs[k4 * 4 + 2][row] = v.z;
      Xs[k4 * 4 + 3][row] = v.w;
    }
    // load W tile: Ws[k][col]
    #pragma unroll
    for (int it = 0; it < 2; it++) {
      int f = tid + it * 256;                 // 512 float4 slots
      int k = f >> 4, c4 = f & 15;
      *(float4*)&Ws[k][c4 * 4] = *(const float4*)&W[(size_t)(kk + k) * 256 + col0 + c4 * 4];
    }
    __syncthreads();
    #pragma unroll
    for (int k = 0; k < 32; k++) {
      union { float4 f; ull u[2]; } A0, A1;
      A0.f = *(const float4*)&Xs[k][ty * 8];
      A1.f = *(const float4*)&Xs[k][ty * 8 + 4];
      float4 bb = *(const float4*)&Ws[k][tx * 4];
      ull au[4] = { A0.u[0], A0.u[1], A1.u[0], A1.u[1] };
      ull bp[4] = { pack2(bb.x, bb.x), pack2(bb.y, bb.y),
                    pack2(bb.z, bb.z), pack2(bb.w, bb.w) };
      #pragma unroll
      for (int i = 0; i < 4; i++)
        #pragma unroll
        for (int j = 0; j < 4; j++) ffma2(acc[i][j], au[i], bp[j]);
    }
    __syncthreads();
  }

  // unpack accumulators: hv[row pair][col][parity]
  float hv[4][4][2];
  #pragma unroll
  for (int i = 0; i < 4; i++)
    #pragma unroll
    for (int j = 0; j < 4; j++) {
      float2 f = unpack2(acc[i][j]);
      hv[i][j][0] = f.x; hv[i][j][1] = f.y;
    }

  // fp16 feature store + logit partials
  #pragma unroll
  for (int i = 0; i < 4; i++) {
    #pragma unroll
    for (int p = 0; p < 2; p++) {
      int lr = ty * 8 + i * 2 + p;
      int row = row0 + lr;
      if (row < NNODES) {
        __half2* op = (__half2*)&g_hh[(size_t)row * 256 + col0 + tx * 4];
        op[0] = __floats2half2_rn(hv[i][0][p], hv[i][1][p]);
        op[1] = __floats2half2_rn(hv[i][2][p], hv[i][3][p]);
      }
      float ss = 0.f, sd = 0.f;
      #pragma unroll
      for (int j = 0; j < 4; j++) {
        ss = fmaf(hv[i][j][p], s_as[tx * 4 + j], ss);
        sd = fmaf(hv[i][j][p], s_ad[tx * 4 + j], sd);
      }
      red_s[lr][tx] = ss;
      red_d[lr][tx] = sd;
    }
  }
  __syncthreads();
  if (tid < 128) {
    int row = row0 + tid;
    if (row < NNODES) {
      float s = 0.f, d = 0.f;
      #pragma unroll
      for (int t = 0; t < 16; t++) { s += red_s[tid][t]; d += red_d[tid][t]; }
      g_als[row * 4 + hd] = s;
      g_ald[row * 4 + hd] = d;
    }
  }
}

// ---------------- GAT aggregate: softmax over in-edges + weighted sum, head-mean + bias ----------------
// one warp per dst node; fp16 gather with channel map c = 2*lane + 64*head
__global__ void k_aggregate(const float* __restrict__ bias, float* __restrict__ xout_ext,
                            int dst_sel, int relu_flag) {
  float* __restrict__ xout = (dst_sel == 1) ? g_x1 : (dst_sel == 2) ? g_x2 : xout_ext;
  int w = (blockIdx.x * blockDim.x + threadIdx.x) >> 5;
  int lane = threadIdx.x & 31;
  if (w >= NNODES) return;
  int beg = g_rowptr[w], end = g_rowptr[w + 1];
  const float4* __restrict__ als4 = (const float4*)g_als;
  float4 ad = ((const float4*)g_ald)[w];

  // pass 1: per-head max of leaky-relu'd logits
  float m0 = -1e30f, m1 = -1e30f, m2 = -1e30f, m3 = -1e30f;
  for (int e = beg + lane; e < end; e += 32) {
    float4 as = als4[g_csr[e]];
    m0 = fmaxf(m0, lrelu(as.x + ad.x));
    m1 = fmaxf(m1, lrelu(as.y + ad.y));
    m2 = fmaxf(m2, lrelu(as.z + ad.z));
    m3 = fmaxf(m3, lrelu(as.w + ad.w));
  }
  m0 = warp_max(m0); m1 = warp_max(m1); m2 = warp_max(m2); m3 = warp_max(m3);

  // pass 2: per-head exp-sum
  float s0 = 0.f, s1 = 0.f, s2 = 0.f, s3 = 0.f;
  for (int e = beg + lane; e < end; e += 32) {
    float4 as = als4[g_csr[e]];
    s0 += __expf(lrelu(as.x + ad.x) - m0);
    s1 += __expf(lrelu(as.y + ad.y) - m1);
    s2 += __expf(lrelu(as.z + ad.z) - m2);
    s3 += __expf(lrelu(as.w + ad.w) - m3);
  }
  s0 = warp_sum(s0); s1 = warp_sum(s1); s2 = warp_sum(s2); s3 = warp_sum(s3);
  float i0 = 1.f / s0, i1 = 1.f / s1, i2 = 1.f / s2, i3 = 1.f / s3;

  // pass 3: weighted accumulate; 4x128B coalesced half2 gathers per edge
  const __half2* __restrict__ H2 = (const __half2*)g_hh;
  float2 a0 = make_float2(0.f, 0.f), a1 = a0, a2 = a0, a3 = a0;
  for (int e = beg; e < end; e++) {
    int s = g_csr[e];                      // uniform per warp -> broadcast
    float4 as = als4[s];
    float w0 = __expf(lrelu(as.x + ad.x) - m0) * i0;
    float w1 = __expf(lrelu(as.y + ad.y) - m1) * i1;
    float w2 = __expf(lrelu(as.z + ad.z) - m2) * i2;
    float w3 = __expf(lrelu(as.w + ad.w) - m3) * i3;
    const __half2* hp = H2 + (size_t)s * 128;
    float2 v0 = __half22float2(hp[lane]);
    float2 v1 = __half22float2(hp[32 + lane]);
    float2 v2 = __half22float2(hp[64 + lane]);
    float2 v3 = __half22float2(hp[96 + lane]);
    a0.x = fmaf(w0, v0.x, a0.x); a0.y = fmaf(w0, v0.y, a0.y);
    a1.x = fmaf(w1, v1.x, a1.x); a1.y = fmaf(w1, v1.y, a1.y);
    a2.x = fmaf(w2, v2.x, a2.x); a2.y = fmaf(w2, v2.y, a2.y);
    a3.x = fmaf(w3, v3.x, a3.x); a3.y = fmaf(w3, v3.y, a3.y);
  }
  float2 bv = ((const float2*)bias)[lane];
  float2 o;
  o.x = (a0.x + a1.x + a2.x + a3.x) * 0.25f + bv.x;
  o.y = (a0.y + a1.y + a2.y + a3.y) * 0.25f + bv.y;
  if (relu_flag) { o.x = fmaxf(o.x, 0.f); o.y = fmaxf(o.y, 0.f); }
  ((float2*)xout)[(size_t)w * 32 + lane] = o;
}

// ---------------- per-node MLP heads (anomaly/risk sigmoid, resource 5-dim) ----------------
__global__ void k_heads(const float* __restrict__ emb,
                        const float* __restrict__ aw1, const float* __restrict__ ab1,
                        const float* __restrict__ aw2, const float* __restrict__ ab2,
                        const float* __restrict__ rw1, const float* __restrict__ rb1,
                        const float* __restrict__ rw2, const float* __restrict__ rb2,
                        const float* __restrict__ cw1, const float* __restrict__ cb1,
                        const float* __restrict__ cw2, const float* __restrict__ cb2,
                        float* __restrict__ anomaly, float* __restrict__ risk,
                        float* __restrict__ resource) {
  __shared__ float s_a1[2048], s_r1[2048], s_c1[2048];
  __shared__ float s_a2[32], s_r2[32], s_c2[160];
  __shared__ float s_ab1[32], s_rb1[32], s_cb1[32];
  __shared__ float s_ab2, s_rb2, s_cb2[5];
  int tid = threadIdx.x;
  for (int t = tid; t < 2048; t += blockDim.x) { s_a1[t] = aw1[t]; s_r1[t] = rw1[t]; s_c1[t] = cw1[t]; }
  for (int t = tid; t < 160; t += blockDim.x) s_c2[t] = cw2[t];
  if (tid < 32) { s_a2[tid] = aw2[tid]; s_r2[tid] = rw2[tid];
                  s_ab1[tid] = ab1[tid]; s_rb1[tid] = rb1[tid]; s_cb1[tid] = cb1[tid]; }
  if (tid == 0) { s_ab2 = ab2[0]; s_rb2 = rb2[0]; }
  if (tid < 5) s_cb2[tid] = cb2[tid];
  __syncthreads();
  int w = (blockIdx.x * blockDim.x + tid) >> 5;
  int lane = tid & 31;
  if (w >= NNODES) return;
  float e0 = emb[(size_t)w * 64 + lane];
  float e1 = emb[(size_t)w * 64 + 32 + lane];
  float ha = s_ab1[lane], hr = s_rb1[lane], hc = s_cb1[lane];
  #pragma unroll
  for (int c = 0; c < 32; c++) {
    float x = __shfl_sync(0xffffffffu, e0, c);
    ha = fmaf(x, s_a1[c * 32 + lane], ha);
    hr = fmaf(x, s_r1[c * 32 + lane], hr);
    hc = fmaf(x, s_c1[c * 32 + lane], hc);
  }
  #pragma unroll
  for (int c = 0; c < 32; c++) {
    float x = __shfl_sync(0xffffffffu, e1, c);
    ha = fmaf(x, s_a1[(c + 32) * 32 + lane], ha);
    hr = fmaf(x, s_r1[(c + 32) * 32 + lane], hr);
    hc = fmaf(x, s_c1[(c + 32) * 32 + lane], hc);
  }
  ha = fmaxf(ha, 0.f); hr = fmaxf(hr, 0.f); hc = fmaxf(hc, 0.f);
  float pa = warp_sum(ha * s_a2[lane]);
  float pr = warp_sum(hr * s_r2[lane]);
  if (lane == 0) {
    anomaly[w] = 1.f / (1.f + __expf(-(pa + s_ab2)));
    risk[w]    = 1.f / (1.f + __expf(-(pr + s_rb2)));
  }
  #pragma unroll
  for (int o = 0; o < 5; o++) {
    float p = warp_sum(hc * s_c2[lane * 5 + o]);
    if (lane == 0) resource[(size_t)w * 5 + o] = p + s_cb2[o];
  }
}

// ---------------- global mean pool (batch is sorted) + graph MLP ----------------
__global__ void k_pool(const float* __restrict__ emb, const int* __restrict__ batch,
                       const float* __restrict__ gw1, const float* __restrict__ gb1,
                       const float* __restrict__ gw2, const float* __restrict__ gb2,
                       float* __restrict__ glog) {
  __shared__ float part[256];
  __shared__ float pooled[64];
  __shared__ float hidden[32];
  __shared__ int s_lo, s_hi;
  int g = blockIdx.x;
  int tid = threadIdx.x;
  if (tid == 0) {
    int lo = 0, hi = NNODES;
    while (lo < hi) { int mid = (lo + hi) >> 1; if (batch[mid] < g) lo = mid + 1; else hi = mid; }
    int lo2 = lo, hi2 = NNODES;
    while (lo2 < hi2) { int mid = (lo2 + hi2) >> 1; if (batch[mid] <= g) lo2 = mid + 1; else hi2 = mid; }
    s_lo = lo; s_hi = lo2;
  }
  __syncthreads();
  int lo = s_lo, hi = s_hi;
  int c = tid & 63, sub = tid >> 6;
  float acc = 0.f;
  for (int i = lo + sub; i < hi; i += 4) acc += emb[(size_t)i * 64 + c];
  part[tid] = acc;
  __syncthreads();
  if (tid < 64) {
    float cnt = fmaxf((float)(hi - lo), 1.f);
    pooled[tid] = (part[tid] + part[tid + 64] + part[tid + 128] + part[tid + 192]) / cnt;
  }
  __syncthreads();
  if (tid < 32) {
    float h = gb1[tid];
    #pragma unroll
    for (int cc = 0; cc < 64; cc++) h = fmaf(pooled[cc], gw1[cc * 32 + tid], h);
    hidden[tid] = fmaxf(h, 0.f);
  }
  __syncthreads();
  if (tid < 4) {
    float o = gb2[tid];
    #pragma unroll
    for (int j = 0; j < 32; j++) o = fmaf(hidden[j], gw2[j * 4 + tid], o);
    glog[g * 4 + tid] = o;
  }
}

// ---------------- launch ----------------
extern "C" void kernel_launch(void* const* d_in, const int* in_sizes, int n_in,
                              void* d_out, int out_size) {
  const float* x     = (const float*)d_in[0];
  const int*   ei    = (const int*)d_in[1];
  const int*   batch = (const int*)d_in[2];
  const float* W1  = (const float*)d_in[3];
  const float* as1 = (const float*)d_in[4];
  const float* ad1 = (const float*)d_in[5];
  const float* b1  = (const float*)d_in[6];
  const float* W2  = (const float*)d_in[7];
  const float* as2 = (const float*)d_in[8];
  const float* ad2 = (const float*)d_in[9];
  const float* b2  = (const float*)d_in[10];
  const float* W3  = (const float*)d_in[11];
  const float* as3 = (const float*)d_in[12];
  const float* ad3 = (const float*)d_in[13];
  const float* b3  = (const float*)d_in[14];
  const float* aw1 = (const float*)d_in[15];
  const float* ab1 = (const float*)d_in[16];
  const float* aw2 = (const float*)d_in[17];
  const float* ab2 = (const float*)d_in[18];
  const float* rw1 = (const float*)d_in[19];
  const float* rb1 = (const float*)d_in[20];
  const float* rw2 = (const float*)d_in[21];
  const float* rb2 = (const float*)d_in[22];
  const float* cw1 = (const float*)d_in[23];
  const float* cb1 = (const float*)d_in[24];
  const float* cw2 = (const float*)d_in[25];
  const float* cb2 = (const float*)d_in[26];
  const float* gw1 = (const float*)d_in[27];
  const float* gb1 = (const float*)d_in[28];
  const float* gw2 = (const float*)d_in[29];
  const float* gb2 = (const float*)d_in[30];

  float* out      = (float*)d_out;
  float* emb      = out;                               // [N,64]
  float* anomaly  = emb + (size_t)NNODES * 64;         // [N]
  float* risk     = anomaly + NNODES;                  // [N]
  float* resource = risk + NNODES;                     // [N,5]
  float* glog     = resource + (size_t)NNODES * 5;     // [G,4]

  // CSR build (dst-grouped, self-loops included)
  k_zero_counts<<<(NNODES + 255) / 256, 256>>>();
  k_count<<<(NETOT + 255) / 256, 256>>>(ei);
  k_scan1<<<NBLK_SCAN, 256>>>();
  k_scan2<<<1, 256>>>();
  k_scan3<<<(NNODES + 255) / 256, 256>>>();
  k_fill<<<(NETOT + 255) / 256, 256>>>(ei);

  dim3 gemm_grid(4, (NNODES + 127) / 128);
  int warp_blocks = (NNODES * 32 + 255) / 256;

  // Layer 1
  k_gemm_fused<128><<<gemm_grid, 256>>>(x, 0, W1, as1, ad1);
  k_aggregate<<<warp_blocks, 256>>>(b1, nullptr, 1, 1);   // -> g_x1, relu
  // Layer 2
  k_gemm_fused<64><<<gemm_grid, 256>>>(nullptr, 1, W2, as2, ad2);
  k_aggregate<<<warp_blocks, 256>>>(b2, nullptr, 2, 1);   // -> g_x2, relu
  // Layer 3
  k_gemm_fused<64><<<gemm_grid, 256>>>(nullptr, 2, W3, as3, ad3);
  k_aggregate<<<warp_blocks, 256>>>(b3, emb, 0, 0);       // -> emb (d_out), no relu

  // Heads + pooling
  k_heads<<<(NNODES * 32 + 511) / 512, 512>>>(emb, aw1, ab1, aw2, ab2,
                                              rw1, rb1, rw2, rb2,
                                              cw1, cb1, cw2, cb2,
                                              anomaly, risk, resource);
  k_pool<<<NGRAPH, 256>>>(emb, batch, gw1, gb1, gw2, gb2, glog);
}

// round 3
// speedup vs baseline: 2.9748x; 1.3336x over previous
#include <cuda_runtime.h>
#include <cuda_fp16.h>
#include <math.h>

#define NNODES 50000
#define NEDGES 800000
#define NETOT  (NEDGES + NNODES)
#define NGRAPH 64
#define NBLK_SCAN ((NNODES + 255) / 256)   // 196

// ---------------- scratch (device globals; no allocation allowed) ----------------
__device__ __half g_hh[NNODES * 256];    // projected features, fp16 [N, H*C]
__device__ __half g_xh1[NNODES * 128];   // layer-1 input, fp16
__device__ __half g_xh[NNODES * 64];     // layer-2/3 input, fp16
__device__ float g_als[NNODES * 4];      // src attention logit per head
__device__ float g_ald[NNODES * 4];      // dst attention logit per head
__device__ int   g_deg[NNODES];
__device__ int   g_rowptr[NNODES + 1];
__device__ int   g_cursor[NNODES];
__device__ int   g_bsum[256];
__device__ int   g_csr[NETOT];           // src index per in-edge, grouped by dst

// ---------------- helpers ----------------
__device__ __forceinline__ float warp_sum(float v) {
  #pragma unroll
  for (int o = 16; o; o >>= 1) v += __shfl_xor_sync(0xffffffffu, v, o);
  return v;
}
__device__ __forceinline__ float lrelu(float v) { return v > 0.f ? v : 0.2f * v; }

// ---------------- CSR build ----------------
__global__ void k_zero_counts() {
  int i = blockIdx.x * blockDim.x + threadIdx.x;
  if (i < NNODES) g_deg[i] = 0;
}

__global__ void k_count(const int* __restrict__ ei) {
  int i = blockIdx.x * blockDim.x + threadIdx.x;
  if (i >= NETOT) return;
  int d = (i < NEDGES) ? ei[NEDGES + i] : (i - NEDGES);   // self-loops appended
  atomicAdd(&g_deg[d], 1);
}

__global__ void k_scan1() {
  __shared__ int tmp[256];
  int tid = threadIdx.x;
  int i = blockIdx.x * 256 + tid;
  int v = (i < NNODES) ? g_deg[i] : 0;
  tmp[tid] = v;
  __syncthreads();
  #pragma unroll
  for (int d = 1; d < 256; d <<= 1) {
    int t = (tid >= d) ? tmp[tid - d] : 0;
    __syncthreads();
    tmp[tid] += t;
    __syncthreads();
  }
  if (i < NNODES) g_rowptr[i] = tmp[tid] - v;   // exclusive within block
  if (tid == 255) g_bsum[blockIdx.x] = tmp[255];
}

__global__ void k_scan2() {
  __shared__ int tmp[256];
  int tid = threadIdx.x;
  int v = (tid < NBLK_SCAN) ? g_bsum[tid] : 0;
  tmp[tid] = v;
  __syncthreads();
  #pragma unroll
  for (int d = 1; d < 256; d <<= 1) {
    int t = (tid >= d) ? tmp[tid - d] : 0;
    __syncthreads();
    tmp[tid] += t;
    __syncthreads();
  }
  g_bsum[tid] = tmp[tid] - v;
}

__global__ void k_scan3() {
  int i = blockIdx.x * blockDim.x + threadIdx.x;
  if (i < NNODES) {
    int v = g_rowptr[i] + g_bsum[i >> 8];
    g_rowptr[i] = v;
    g_cursor[i] = v;                    // fill cursor starts at row offset
  }
  if (i == 0) g_rowptr[NNODES] = NETOT;
}

__global__ void k_fill(const int* __restrict__ ei) {
  int i = blockIdx.x * blockDim.x + threadIdx.x;
  if (i >= NETOT) return;
  int s, d;
  if (i < NEDGES) { s = ei[i]; d = ei[NEDGES + i]; }
  else            { s = i - NEDGES; d = s; }
  int pos = atomicAdd(&g_cursor[d], 1);
  g_csr[pos] = s;
}

// ---------------- layer-1 input cast fp32 -> fp16 ----------------
__global__ void k_xcast(const float* __restrict__ x) {
  int i = blockIdx.x * blockDim.x + threadIdx.x;   // float4 index
  if (i >= NNODES * 32) return;
  float4 v = ((const float4*)x)[i];
  __half2* o = (__half2*)g_xh1;
  o[i * 2]     = __floats2half2_rn(v.x, v.y);
  o[i * 2 + 1] = __floats2half2_rn(v.z, v.w);
}

// ---------------- tensor-core GEMM + logit epilogue ----------------
// h = X[N,K](fp16) @ W[K,256](fp32->fp16); block tile 128 x 64 (one head),
// 8 warps (4 m x 2 n), warp tile 32x32, mma.m16n8k16 fp16 -> fp32.
// Epilogue: fp16 store of h + per-row attention logits for this head.
__device__ __forceinline__ void ldsm4(unsigned& r0, unsigned& r1, unsigned& r2, unsigned& r3,
                                      unsigned addr) {
  asm volatile("ldmatrix.sync.aligned.m8n8.x4.shared.b16 {%0,%1,%2,%3}, [%4];"
               : "=r"(r0), "=r"(r1), "=r"(r2), "=r"(r3) : "r"(addr));
}
__device__ __forceinline__ void ldsm2t(unsigned& r0, unsigned& r1, unsigned addr) {
  asm volatile("ldmatrix.sync.aligned.m8n8.x2.trans.shared.b16 {%0,%1}, [%2];"
               : "=r"(r0), "=r"(r1) : "r"(addr));
}
__device__ __forceinline__ void mma16816(float* c, const unsigned* a, const unsigned* b) {
  asm volatile("mma.sync.aligned.m16n8k16.row.col.f32.f16.f16.f32 "
               "{%0,%1,%2,%3},{%4,%5,%6,%7},{%8,%9},{%0,%1,%2,%3};"
               : "+f"(c[0]), "+f"(c[1]), "+f"(c[2]), "+f"(c[3])
               : "r"(a[0]), "r"(a[1]), "r"(a[2]), "r"(a[3]), "r"(b[0]), "r"(b[1]));
}

template<int K>
__global__ void __launch_bounds__(256) k_gemm_mma(
    int src_sel, const float* __restrict__ W,
    const float* __restrict__ a_s, const float* __restrict__ a_d) {
  constexpr int APAD = K + 8;               // halves per A row
  constexpr int A_BYTES = 128 * APAD * 2;
  constexpr int B_BYTES = K * 72 * 2;
  extern __shared__ __align__(16) char dyn[];
  __half* As = (__half*)dyn;                 // [128][APAD]
  __half* Bs = (__half*)(dyn + A_BYTES);     // [K][72]
  float* s_as = (float*)(dyn + A_BYTES + B_BYTES);
  float* s_ad = s_as + 64;
  float* red_s = (float*)dyn;                // overlay after mma: [128][2]
  float* red_d = (float*)(dyn + 1024);

  const __half* __restrict__ X = (src_sel == 0) ? g_xh1 : g_xh;
  int tid = threadIdx.x;
  int lane = tid & 31, wid = tid >> 5;
  int warp_m = wid >> 1, warp_n = wid & 1;
  int hd = blockIdx.x;
  int col0 = hd * 64;
  int row0 = blockIdx.y * 128;

  if (tid < 64) { s_as[tid] = a_s[col0 + tid]; s_ad[tid] = a_d[col0 + tid]; }

  // load A [128 x K] fp16 (zero-fill OOB rows)
  constexpr int A_IT = 128 * K / 8 / 256;
  #pragma unroll
  for (int it = 0; it < A_IT; it++) {
    int idx = tid + it * 256;
    int r = idx / (K / 8), c8 = idx % (K / 8);
    uint4 v = make_uint4(0, 0, 0, 0);
    if (row0 + r < NNODES)
      v = *(const uint4*)&X[(size_t)(row0 + r) * K + c8 * 8];
    *(uint4*)&As[r * APAD + c8 * 8] = v;
  }
  // load + convert B [K x 64]
  constexpr int B_IT = K * 16 / 256;
  #pragma unroll
  for (int it = 0; it < B_IT; it++) {
    int idx = tid + it * 256;
    int k = idx >> 4, c4 = idx & 15;
    float4 v = *(const float4*)&W[(size_t)k * 256 + col0 + c4 * 4];
    __half2* o = (__half2*)&Bs[k * 72 + c4 * 4];
    o[0] = __floats2half2_rn(v.x, v.y);
    o[1] = __floats2half2_rn(v.z, v.w);
  }
  __syncthreads();

  unsigned As_u = (unsigned)__cvta_generic_to_shared(As);
  unsigned Bs_u = (unsigned)__cvta_generic_to_shared(Bs);
  unsigned a_base = As_u + ((warp_m * 32 + (lane & 15)) * APAD + (lane >> 4) * 8) * 2;
  unsigned b_base = Bs_u + ((lane & 15) * 72 + warp_n * 32) * 2;

  float acc[2][4][4];
  #pragma unroll
  for (int mt = 0; mt < 2; mt++)
    #pragma unroll
    for (int nt = 0; nt < 4; nt++)
      #pragma unroll
      for (int q = 0; q < 4; q++) acc[mt][nt][q] = 0.f;

  #pragma unroll
  for (int ks = 0; ks < K / 16; ks++) {
    unsigned a[2][4], b[4][2];
    #pragma unroll
    for (int mt = 0; mt < 2; mt++)
      ldsm4(a[mt][0], a[mt][1], a[mt][2], a[mt][3],
            a_base + (mt * 16 * APAD + ks * 16) * 2);
    #pragma unroll
    for (int nt = 0; nt < 4; nt++)
      ldsm2t(b[nt][0], b[nt][1], b_base + (ks * 16 * 72 + nt * 8) * 2);
    #pragma unroll
    for (int mt = 0; mt < 2; mt++)
      #pragma unroll
      for (int nt = 0; nt < 4; nt++)
        mma16816(acc[mt][nt], a[mt], b[nt]);
  }
  __syncthreads();   // reds overlay As

  int quad = lane >> 2, qid = lane & 3;
  #pragma unroll
  for (int mt = 0; mt < 2; mt++) {
    #pragma unroll
    for (int rh = 0; rh < 2; rh++) {
      int lr = warp_m * 32 + mt * 16 + rh * 8 + quad;
      int row = row0 + lr;
      float ss = 0.f, sd = 0.f;
      #pragma unroll
      for (int nt = 0; nt < 4; nt++) {
        float v0 = acc[mt][nt][rh * 2 + 0];
        float v1 = acc[mt][nt][rh * 2 + 1];
        int c = warp_n * 32 + nt * 8 + qid * 2;
        ss = fmaf(v0, s_as[c], fmaf(v1, s_as[c + 1], ss));
        sd = fmaf(v0, s_ad[c], fmaf(v1, s_ad[c + 1], sd));
        if (row < NNODES)
          *(__half2*)&g_hh[(size_t)row * 256 + col0 + c] = __floats2half2_rn(v0, v1);
      }
      ss += __shfl_xor_sync(0xffffffffu, ss, 1);
      ss += __shfl_xor_sync(0xffffffffu, ss, 2);
      sd += __shfl_xor_sync(0xffffffffu, sd, 1);
      sd += __shfl_xor_sync(0xffffffffu, sd, 2);
      if (qid == 0) { red_s[lr * 2 + warp_n] = ss; red_d[lr * 2 + warp_n] = sd; }
    }
  }
  __syncthreads();
  if (tid < 128) {
    int row = row0 + tid;
    if (row < NNODES) {
      g_als[row * 4 + hd] = red_s[tid * 2] + red_s[tid * 2 + 1];
      g_ald[row * 4 + hd] = red_d[tid * 2] + red_d[tid * 2 + 1];
    }
  }
}

// ---------------- GAT aggregate: single-pass softmax-weighted sum ----------------
// alpha = exp(lrelu(logit)) / sum(exp(...)) -- normalization folded to the end.
// one warp per dst node; fp16 gather, channel pair = 2*lane within each head.
__global__ void k_aggregate(const float* __restrict__ bias, float* __restrict__ xout,
                            int fp16_relu) {
  int w = (blockIdx.x * blockDim.x + threadIdx.x) >> 5;
  int lane = threadIdx.x & 31;
  if (w >= NNODES) return;
  int beg = g_rowptr[w], end = g_rowptr[w + 1];
  const float4* __restrict__ als4 = (const float4*)g_als;
  float4 ad = ((const float4*)g_ald)[w];
  const __half2* __restrict__ H2 = (const __half2*)g_hh;

  float d0 = 0.f, d1 = 0.f, d2 = 0.f, d3 = 0.f;
  float2 a0 = make_float2(0.f, 0.f), a1 = a0, a2 = a0, a3 = a0;
  for (int e = beg; e < end; e++) {
    int s = g_csr[e];                      // uniform per warp -> broadcast
    float4 as = als4[s];
    float p0 = __expf(lrelu(as.x + ad.x));
    float p1 = __expf(lrelu(as.y + ad.y));
    float p2 = __expf(lrelu(as.z + ad.z));
    float p3 = __expf(lrelu(as.w + ad.w));
    const __half2* hp = H2 + (size_t)s * 128;
    float2 v0 = __half22float2(hp[lane]);
    float2 v1 = __half22float2(hp[32 + lane]);
    float2 v2 = __half22float2(hp[64 + lane]);
    float2 v3 = __half22float2(hp[96 + lane]);
    d0 += p0; d1 += p1; d2 += p2; d3 += p3;
    a0.x = fmaf(p0, v0.x, a0.x); a0.y = fmaf(p0, v0.y, a0.y);
    a1.x = fmaf(p1, v1.x, a1.x); a1.y = fmaf(p1, v1.y, a1.y);
    a2.x = fmaf(p2, v2.x, a2.x); a2.y = fmaf(p2, v2.y, a2.y);
    a3.x = fmaf(p3, v3.x, a3.x); a3.y = fmaf(p3, v3.y, a3.y);
  }
  float r0 = 1.f / d0, r1 = 1.f / d1, r2 = 1.f / d2, r3 = 1.f / d3;
  float2 bv = ((const float2*)bias)[lane];
  float2 o;
  o.x = (a0.x * r0 + a1.x * r1 + a2.x * r2 + a3.x * r3) * 0.25f + bv.x;
  o.y = (a0.y * r0 + a1.y * r1 + a2.y * r2 + a3.y * r3) * 0.25f + bv.y;
  if (fp16_relu) {
    o.x = fmaxf(o.x, 0.f); o.y = fmaxf(o.y, 0.f);
    ((__half2*)g_xh)[(size_t)w * 32 + lane] = __floats2half2_rn(o.x, o.y);
  } else {
    ((float2*)xout)[(size_t)w * 32 + lane] = o;
  }
}

// ---------------- per-node MLP heads ----------------
__global__ void k_heads(const float* __restrict__ emb,
                        const float* __restrict__ aw1, const float* __restrict__ ab1,
                        const float* __restrict__ aw2, const float* __restrict__ ab2,
                        const float* __restrict__ rw1, const float* __restrict__ rb1,
                        const float* __restrict__ rw2, const float* __restrict__ rb2,
                        const float* __restrict__ cw1, const float* __restrict__ cb1,
                        const float* __restrict__ cw2, const float* __restrict__ cb2,
                        float* __restrict__ anomaly, float* __restrict__ risk,
                        float* __restrict__ resource) {
  __shared__ float s_a1[2048], s_r1[2048], s_c1[2048];
  __shared__ float s_a2[32], s_r2[32], s_c2[160];
  __shared__ float s_ab1[32], s_rb1[32], s_cb1[32];
  __shared__ float s_ab2, s_rb2, s_cb2[5];
  int tid = threadIdx.x;
  for (int t = tid; t < 2048; t += blockDim.x) { s_a1[t] = aw1[t]; s_r1[t] = rw1[t]; s_c1[t] = cw1[t]; }
  for (int t = tid; t < 160; t += blockDim.x) s_c2[t] = cw2[t];
  if (tid < 32) { s_a2[tid] = aw2[tid]; s_r2[tid] = rw2[tid];
                  s_ab1[tid] = ab1[tid]; s_rb1[tid] = rb1[tid]; s_cb1[tid] = cb1[tid]; }
  if (tid == 0) { s_ab2 = ab2[0]; s_rb2 = rb2[0]; }
  if (tid < 5) s_cb2[tid] = cb2[tid];
  __syncthreads();
  int w = (blockIdx.x * blockDim.x + tid) >> 5;
  int lane = tid & 31;
  if (w >= NNODES) return;
  float e0 = emb[(size_t)w * 64 + lane];
  float e1 = emb[(size_t)w * 64 + 32 + lane];
  float ha = s_ab1[lane], hr = s_rb1[lane], hc = s_cb1[lane];
  #pragma unroll
  for (int c = 0; c < 32; c++) {
    float x = __shfl_sync(0xffffffffu, e0, c);
    ha = fmaf(x, s_a1[c * 32 + lane], ha);
    hr = fmaf(x, s_r1[c * 32 + lane], hr);
    hc = fmaf(x, s_c1[c * 32 + lane], hc);
  }
  #pragma unroll
  for (int c = 0; c < 32; c++) {
    float x = __shfl_sync(0xffffffffu, e1, c);
    ha = fmaf(x, s_a1[(c + 32) * 32 + lane], ha);
    hr = fmaf(x, s_r1[(c + 32) * 32 + lane], hr);
    hc = fmaf(x, s_c1[(c + 32) * 32 + lane], hc);
  }
  ha = fmaxf(ha, 0.f); hr = fmaxf(hr, 0.f); hc = fmaxf(hc, 0.f);
  float pa = warp_sum(ha * s_a2[lane]);
  float pr = warp_sum(hr * s_r2[lane]);
  if (lane == 0) {
    anomaly[w] = 1.f / (1.f + __expf(-(pa + s_ab2)));
    risk[w]    = 1.f / (1.f + __expf(-(pr + s_rb2)));
  }
  #pragma unroll
  for (int o = 0; o < 5; o++) {
    float p = warp_sum(hc * s_c2[lane * 5 + o]);
    if (lane == 0) resource[(size_t)w * 5 + o] = p + s_cb2[o];
  }
}

// ---------------- global mean pool + graph MLP ----------------
__global__ void k_pool(const float* __restrict__ emb, const int* __restrict__ batch,
                       const float* __restrict__ gw1, const float* __restrict__ gb1,
                       const float* __restrict__ gw2, const float* __restrict__ gb2,
                       float* __restrict__ glog) {
  __shared__ float part[256];
  __shared__ float pooled[64];
  __shared__ float hidden[32];
  __shared__ int s_lo, s_hi;
  int g = blockIdx.x;
  int tid = threadIdx.x;
  if (tid == 0) {
    int lo = 0, hi = NNODES;
    while (lo < hi) { int mid = (lo + hi) >> 1; if (batch[mid] < g) lo = mid + 1; else hi = mid; }
    int lo2 = lo, hi2 = NNODES;
    while (lo2 < hi2) { int mid = (lo2 + hi2) >> 1; if (batch[mid] <= g) lo2 = mid + 1; else hi2 = mid; }
    s_lo = lo; s_hi = lo2;
  }
  __syncthreads();
  int lo = s_lo, hi = s_hi;
  int c = tid & 63, sub = tid >> 6;
  float acc = 0.f;
  for (int i = lo + sub; i < hi; i += 4) acc += emb[(size_t)i * 64 + c];
  part[tid] = acc;
  __syncthreads();
  if (tid < 64) {
    float cnt = fmaxf((float)(hi - lo), 1.f);
    pooled[tid] = (part[tid] + part[tid + 64] + part[tid + 128] + part[tid + 192]) / cnt;
  }
  __syncthreads();
  if (tid < 32) {
    float h = gb1[tid];
    #pragma unroll
    for (int cc = 0; cc < 64; cc++) h = fmaf(pooled[cc], gw1[cc * 32 + tid], h);
    hidden[tid] = fmaxf(h, 0.f);
  }
  __syncthreads();
  if (tid < 4) {
    float o = gb2[tid];
    #pragma unroll
    for (int j = 0; j < 32; j++) o = fmaf(hidden[j], gw2[j * 4 + tid], o);
    glog[g * 4 + tid] = o;
  }
}

// ---------------- launch ----------------
extern "C" void kernel_launch(void* const* d_in, const int* in_sizes, int n_in,
                              void* d_out, int out_size) {
  const float* x     = (const float*)d_in[0];
  const int*   ei    = (const int*)d_in[1];
  const int*   batch = (const int*)d_in[2];
  const float* W1  = (const float*)d_in[3];
  const float* as1 = (const float*)d_in[4];
  const float* ad1 = (const float*)d_in[5];
  const float* b1  = (const float*)d_in[6];
  const float* W2  = (const float*)d_in[7];
  const float* as2 = (const float*)d_in[8];
  const float* ad2 = (const float*)d_in[9];
  const float* b2  = (const float*)d_in[10];
  const float* W3  = (const float*)d_in[11];
  const float* as3 = (const float*)d_in[12];
  const float* ad3 = (const float*)d_in[13];
  const float* b3  = (const float*)d_in[14];
  const float* aw1 = (const float*)d_in[15];
  const float* ab1 = (const float*)d_in[16];
  const float* aw2 = (const float*)d_in[17];
  const float* ab2 = (const float*)d_in[18];
  const float* rw1 = (const float*)d_in[19];
  const float* rb1 = (const float*)d_in[20];
  const float* rw2 = (const float*)d_in[21];
  const float* rb2 = (const float*)d_in[22];
  const float* cw1 = (const float*)d_in[23];
  const float* cb1 = (const float*)d_in[24];
  const float* cw2 = (const float*)d_in[25];
  const float* cb2 = (const float*)d_in[26];
  const float* gw1 = (const float*)d_in[27];
  const float* gb1 = (const float*)d_in[28];
  const float* gw2 = (const float*)d_in[29];
  const float* gb2 = (const float*)d_in[30];

  float* out      = (float*)d_out;
  float* emb      = out;                               // [N,64]
  float* anomaly  = emb + (size_t)NNODES * 64;         // [N]
  float* risk     = anomaly + NNODES;                  // [N]
  float* resource = risk + NNODES;                     // [N,5]
  float* glog     = resource + (size_t)NNODES * 5;     // [G,4]

  const int SMEM128 = 128 * 136 * 2 + 128 * 72 * 2 + 512;   // 53760
  const int SMEM64  = 128 * 72 * 2 + 64 * 72 * 2 + 512;     // 28160
  cudaFuncSetAttribute(k_gemm_mma<128>, cudaFuncAttributeMaxDynamicSharedMemorySize, SMEM128);
  cudaFuncSetAttribute(k_gemm_mma<64>,  cudaFuncAttributeMaxDynamicSharedMemorySize, SMEM64);

  // CSR build (dst-grouped, self-loops included)
  k_zero_counts<<<(NNODES + 255) / 256, 256>>>();
  k_count<<<(NETOT + 255) / 256, 256>>>(ei);
  k_scan1<<<NBLK_SCAN, 256>>>();
  k_scan2<<<1, 256>>>();
  k_scan3<<<(NNODES + 255) / 256, 256>>>();
  k_fill<<<(NETOT + 255) / 256, 256>>>(ei);
  k_xcast<<<(NNODES * 32 + 255) / 256, 256>>>(x);

  dim3 gemm_grid(4, (NNODES + 127) / 128);
  int warp_blocks = (NNODES * 32 + 255) / 256;

  // Layer 1
  k_gemm_mma<128><<<gemm_grid, 256, SMEM128>>>(0, W1, as1, ad1);
  k_aggregate<<<warp_blocks, 256>>>(b1, nullptr, 1);      // -> g_xh fp16 + relu
  // Layer 2
  k_gemm_mma<64><<<gemm_grid, 256, SMEM64>>>(1, W2, as2, ad2);
  k_aggregate<<<warp_blocks, 256>>>(b2, nullptr, 1);      // -> g_xh fp16 + relu
  // Layer 3
  k_gemm_mma<64><<<gemm_grid, 256, SMEM64>>>(1, W3, as3, ad3);
  k_aggregate<<<warp_blocks, 256>>>(b3, emb, 0);          // -> emb fp32, no relu

  // Heads + pooling
  k_heads<<<(NNODES * 32 + 511) / 512, 512>>>(emb, aw1, ab1, aw2, ab2,
                                              rw1, rb1, rw2, rb2,
                                              cw1, cb1, cw2, cb2,
                                              anomaly, risk, resource);
  k_pool<<<NGRAPH, 256>>>(emb, batch, gw1, gb1, gw2, gb2, glog);
}

// round 4
// speedup vs baseline: 3.2422x; 1.0899x over previous
#include <cuda_runtime.h>
#include <cuda_fp16.h>
#include <math.h>

#define NNODES 50000
#define NEDGES 800000
#define NETOT  (NEDGES + NNODES)
#define NGRAPH 64
#define NBLK_SCAN ((NNODES + 255) / 256)   // 196

// ---------------- scratch (device globals; no allocation allowed) ----------------
__device__ __half g_hh[NNODES * 256];    // projected features fp16; lane-interleaved:
                                         // row halves idx = 8*(c>>1) + 2*head + (c&1)
__device__ __half g_xh1[NNODES * 128];   // layer-1 input, fp16
__device__ __half g_xh[NNODES * 64];     // layer-2/3 input, fp16
__device__ float g_als[NNODES * 4];      // src attention logit per head
__device__ float g_ald[NNODES * 4];      // dst attention logit per head
__device__ float g_ew[NETOT * 4];        // per-edge unnormalized softmax weights
__device__ int   g_deg[NNODES];
__device__ int   g_rowptr[NNODES + 1];
__device__ int   g_cursor[NNODES];
__device__ int   g_bsum[256];
__device__ int   g_csr[NETOT];           // src index per in-edge, grouped by dst
__device__ int   g_dste[NETOT];          // dst index per in-edge

// ---------------- helpers ----------------
__device__ __forceinline__ float warp_sum(float v) {
  #pragma unroll
  for (int o = 16; o; o >>= 1) v += __shfl_xor_sync(0xffffffffu, v, o);
  return v;
}
__device__ __forceinline__ float lrelu(float v) { return v > 0.f ? v : 0.2f * v; }

typedef unsigned long long ull;
__device__ __forceinline__ ull pack2(float x, float y) {
  ull r; asm("mov.b64 %0,{%1,%2};" : "=l"(r) : "f"(x), "f"(y)); return r;
}
__device__ __forceinline__ void ffma2(ull& d, ull a, ull b) {
  asm("fma.rn.f32x2 %0,%1,%2,%0;" : "+l"(d) : "l"(a), "l"(b));
}
__device__ __forceinline__ void fadd2(ull& d, ull a) {
  asm("add.rn.f32x2 %0,%0,%1;" : "+l"(d) : "l"(a));
}
__device__ __forceinline__ float2 unpack2(ull v) {
  float2 f; asm("mov.b64 {%0,%1},%2;" : "=f"(f.x), "=f"(f.y) : "l"(v)); return f;
}

// ---------------- CSR build ----------------
__global__ void k_zero_counts() {
  int i = blockIdx.x * blockDim.x + threadIdx.x;
  if (i < NNODES) g_deg[i] = 0;
}

__global__ void k_count(const int* __restrict__ ei) {
  int i = blockIdx.x * blockDim.x + threadIdx.x;
  if (i >= NETOT) return;
  int d = (i < NEDGES) ? ei[NEDGES + i] : (i - NEDGES);   // self-loops appended
  atomicAdd(&g_deg[d], 1);
}

__global__ void k_scan1() {
  __shared__ int tmp[256];
  int tid = threadIdx.x;
  int i = blockIdx.x * 256 + tid;
  int v = (i < NNODES) ? g_deg[i] : 0;
  tmp[tid] = v;
  __syncthreads();
  #pragma unroll
  for (int d = 1; d < 256; d <<= 1) {
    int t = (tid >= d) ? tmp[tid - d] : 0;
    __syncthreads();
    tmp[tid] += t;
    __syncthreads();
  }
  if (i < NNODES) g_rowptr[i] = tmp[tid] - v;   // exclusive within block
  if (tid == 255) g_bsum[blockIdx.x] = tmp[255];
}

__global__ void k_scan2() {
  __shared__ int tmp[256];
  int tid = threadIdx.x;
  int v = (tid < NBLK_SCAN) ? g_bsum[tid] : 0;
  tmp[tid] = v;
  __syncthreads();
  #pragma unroll
  for (int d = 1; d < 256; d <<= 1) {
    int t = (tid >= d) ? tmp[tid - d] : 0;
    __syncthreads();
    tmp[tid] += t;
    __syncthreads();
  }
  g_bsum[tid] = tmp[tid] - v;
}

__global__ void k_scan3() {
  int i = blockIdx.x * blockDim.x + threadIdx.x;
  if (i < NNODES) {
    int v = g_rowptr[i] + g_bsum[i >> 8];
    g_rowptr[i] = v;
    g_cursor[i] = v;
  }
  if (i == 0) g_rowptr[NNODES] = NETOT;
}

__global__ void k_fill(const int* __restrict__ ei) {
  int i = blockIdx.x * blockDim.x + threadIdx.x;
  if (i >= NETOT) return;
  int s, d;
  if (i < NEDGES) { s = ei[i]; d = ei[NEDGES + i]; }
  else            { s = i - NEDGES; d = s; }
  int pos = atomicAdd(&g_cursor[d], 1);
  g_csr[pos] = s;
  g_dste[pos] = d;
}

// ---------------- layer-1 input cast fp32 -> fp16 ----------------
__global__ void k_xcast(const float* __restrict__ x) {
  int i = blockIdx.x * blockDim.x + threadIdx.x;   // float4 index
  if (i >= NNODES * 32) return;
  float4 v = ((const float4*)x)[i];
  __half2* o = (__half2*)g_xh1;
  o[i * 2]     = __floats2half2_rn(v.x, v.y);
  o[i * 2 + 1] = __floats2half2_rn(v.z, v.w);
}

// ---------------- edge-parallel softmax weights ----------------
__global__ void k_edgew() {
  int e = blockIdx.x * blockDim.x + threadIdx.x;
  if (e >= NETOT) return;
  int s = g_csr[e], d = g_dste[e];
  float4 as = ((const float4*)g_als)[s];
  float4 ad = ((const float4*)g_ald)[d];
  float4 w;
  w.x = __expf(lrelu(as.x + ad.x));
  w.y = __expf(lrelu(as.y + ad.y));
  w.z = __expf(lrelu(as.z + ad.z));
  w.w = __expf(lrelu(as.w + ad.w));
  ((float4*)g_ew)[e] = w;
}

// ---------------- tensor-core GEMM + logit epilogue ----------------
__device__ __forceinline__ void ldsm4(unsigned& r0, unsigned& r1, unsigned& r2, unsigned& r3,
                                      unsigned addr) {
  asm volatile("ldmatrix.sync.aligned.m8n8.x4.shared.b16 {%0,%1,%2,%3}, [%4];"
               : "=r"(r0), "=r"(r1), "=r"(r2), "=r"(r3) : "r"(addr));
}
__device__ __forceinline__ void ldsm2t(unsigned& r0, unsigned& r1, unsigned addr) {
  asm volatile("ldmatrix.sync.aligned.m8n8.x2.trans.shared.b16 {%0,%1}, [%2];"
               : "=r"(r0), "=r"(r1) : "r"(addr));
}
__device__ __forceinline__ void mma16816(float* c, const unsigned* a, const unsigned* b) {
  asm volatile("mma.sync.aligned.m16n8k16.row.col.f32.f16.f16.f32 "
               "{%0,%1,%2,%3},{%4,%5,%6,%7},{%8,%9},{%0,%1,%2,%3};"
               : "+f"(c[0]), "+f"(c[1]), "+f"(c[2]), "+f"(c[3])
               : "r"(a[0]), "r"(a[1]), "r"(a[2]), "r"(a[3]), "r"(b[0]), "r"(b[1]));
}

template<int K>
__global__ void __launch_bounds__(256) k_gemm_mma(
    int src_sel, const float* __restrict__ W,
    const float* __restrict__ a_s, const float* __restrict__ a_d) {
  constexpr int APAD = K + 8;
  constexpr int A_BYTES = 128 * APAD * 2;
  constexpr int B_BYTES = K * 72 * 2;
  extern __shared__ __align__(16) char dyn[];
  __half* As = (__half*)dyn;
  __half* Bs = (__half*)(dyn + A_BYTES);
  float* s_as = (float*)(dyn + A_BYTES + B_BYTES);
  float* s_ad = s_as + 64;
  float* red_s = (float*)dyn;                // overlay after mma: [128][2]
  float* red_d = (float*)(dyn + 1024);

  const __half* __restrict__ X = (src_sel == 0) ? g_xh1 : g_xh;
  int tid = threadIdx.x;
  int lane = tid & 31, wid = tid >> 5;
  int warp_m = wid >> 1, warp_n = wid & 1;
  int hd = blockIdx.x;
  int col0 = hd * 64;
  int row0 = blockIdx.y * 128;

  if (tid < 64) { s_as[tid] = a_s[col0 + tid]; s_ad[tid] = a_d[col0 + tid]; }

  constexpr int A_IT = 128 * K / 8 / 256;
  #pragma unroll
  for (int it = 0; it < A_IT; it++) {
    int idx = tid + it * 256;
    int r = idx / (K / 8), c8 = idx % (K / 8);
    uint4 v = make_uint4(0, 0, 0, 0);
    if (row0 + r < NNODES)
      v = *(const uint4*)&X[(size_t)(row0 + r) * K + c8 * 8];
    *(uint4*)&As[r * APAD + c8 * 8] = v;
  }
  constexpr int B_IT = K * 16 / 256;
  #pragma unroll
  for (int it = 0; it < B_IT; it++) {
    int idx = tid + it * 256;
    int k = idx >> 4, c4 = idx & 15;
    float4 v = *(const float4*)&W[(size_t)k * 256 + col0 + c4 * 4];
    __half2* o = (__half2*)&Bs[k * 72 + c4 * 4];
    o[0] = __floats2half2_rn(v.x, v.y);
    o[1] = __floats2half2_rn(v.z, v.w);
  }
  __syncthreads();

  unsigned As_u = (unsigned)__cvta_generic_to_shared(As);
  unsigned Bs_u = (unsigned)__cvta_generic_to_shared(Bs);
  unsigned a_base = As_u + ((warp_m * 32 + (lane & 15)) * APAD + (lane >> 4) * 8) * 2;
  unsigned b_base = Bs_u + ((lane & 15) * 72 + warp_n * 32) * 2;

  float acc[2][4][4];
  #pragma unroll
  for (int mt = 0; mt < 2; mt++)
    #pragma unroll
    for (int nt = 0; nt < 4; nt++)
      #pragma unroll
      for (int q = 0; q < 4; q++) acc[mt][nt][q] = 0.f;

  #pragma unroll
  for (int ks = 0; ks < K / 16; ks++) {
    unsigned a[2][4], b[4][2];
    #pragma unroll
    for (int mt = 0; mt < 2; mt++)
      ldsm4(a[mt][0], a[mt][1], a[mt][2], a[mt][3],
            a_base + (mt * 16 * APAD + ks * 16) * 2);
    #pragma unroll
    for (int nt = 0; nt < 4; nt++)
      ldsm2t(b[nt][0], b[nt][1], b_base + (ks * 16 * 72 + nt * 8) * 2);
    #pragma unroll
    for (int mt = 0; mt < 2; mt++)
      #pragma unroll
      for (int nt = 0; nt < 4; nt++)
        mma16816(acc[mt][nt], a[mt], b[nt]);
  }
  __syncthreads();   // reds overlay As

  int quad = lane >> 2, qid = lane & 3;
  #pragma unroll
  for (int mt = 0; mt < 2; mt++) {
    #pragma unroll
    for (int rh = 0; rh < 2; rh++) {
      int lr = warp_m * 32 + mt * 16 + rh * 8 + quad;
      int row = row0 + lr;
      float ss = 0.f, sd = 0.f;
      #pragma unroll
      for (int nt = 0; nt < 4; nt++) {
        float v0 = acc[mt][nt][rh * 2 + 0];
        float v1 = acc[mt][nt][rh * 2 + 1];
        int c = warp_n * 32 + nt * 8 + qid * 2;     // local even channel
        ss = fmaf(v0, s_as[c], fmaf(v1, s_as[c + 1], ss));
        sd = fmaf(v0, s_ad[c], fmaf(v1, s_ad[c + 1], sd));
        if (row < NNODES)   // lane-interleaved layout: 8*(c/2) + 2*hd
          *(__half2*)&g_hh[(size_t)row * 256 + c * 4 + hd * 2] = __floats2half2_rn(v0, v1);
      }
      ss += __shfl_xor_sync(0xffffffffu, ss, 1);
      ss += __shfl_xor_sync(0xffffffffu, ss, 2);
      sd += __shfl_xor_sync(0xffffffffu, sd, 1);
      sd += __shfl_xor_sync(0xffffffffu, sd, 2);
      if (qid == 0) { red_s[lr * 2 + warp_n] = ss; red_d[lr * 2 + warp_n] = sd; }
    }
  }
  __syncthreads();
  if (tid < 128) {
    int row = row0 + tid;
    if (row < NNODES) {
      g_als[row * 4 + hd] = red_s[tid * 2] + red_s[tid * 2 + 1];
      g_ald[row * 4 + hd] = red_d[tid * 2] + red_d[tid * 2 + 1];
    }
  }
}

// ---------------- GAT aggregate: weighted sum with precomputed edge weights ----------------
// one warp per dst node; lane l owns channels {2l, 2l+1} of all 4 heads ->
// one uint4 (16B) gather per lane = full 512B feature row per warp per edge.
__global__ void k_aggregate(const float* __restrict__ bias, float* __restrict__ xout,
                            int fp16_relu) {
  int w = (blockIdx.x * blockDim.x + threadIdx.x) >> 5;
  int lane = threadIdx.x & 31;
  if (w >= NNODES) return;
  int beg = g_rowptr[w], end = g_rowptr[w + 1];
  const uint4* __restrict__ H4 = (const uint4*)g_hh;     // 32 uint4 per row
  const float4* __restrict__ EW = (const float4*)g_ew;

  ull acc0 = 0, acc1 = 0, acc2 = 0, acc3 = 0;
  ull dd01 = 0, dd23 = 0;
  for (int e = beg; e < end; e++) {
    int s = g_csr[e];                       // uniform per warp -> broadcast
    float4 wv = EW[e];                      // broadcast 16B
    uint4 hv = H4[(size_t)s * 32 + lane];   // 512B coalesced
    dd01 = dd01;  // keep order
    fadd2(dd01, pack2(wv.x, wv.y));
    fadd2(dd23, pack2(wv.z, wv.w));
    float2 f0 = __half22float2(*(__half2*)&hv.x);
    float2 f1 = __half22float2(*(__half2*)&hv.y);
    float2 f2 = __half22float2(*(__half2*)&hv.z);
    float2 f3 = __half22float2(*(__half2*)&hv.w);
    ffma2(acc0, pack2(f0.x, f0.y), pack2(wv.x, wv.x));
    ffma2(acc1, pack2(f1.x, f1.y), pack2(wv.y, wv.y));
    ffma2(acc2, pack2(f2.x, f2.y), pack2(wv.z, wv.z));
    ffma2(acc3, pack2(f3.x, f3.y), pack2(wv.w, wv.w));
  }
  float2 d01 = unpack2(dd01), d23 = unpack2(dd23);
  float2 a0 = unpack2(acc0), a1 = unpack2(acc1), a2 = unpack2(acc2), a3 = unpack2(acc3);
  float r0 = 1.f / d01.x, r1 = 1.f / d01.y, r2 = 1.f / d23.x, r3 = 1.f / d23.y;
  float2 bv = ((const float2*)bias)[lane];
  float2 o;
  o.x = (a0.x * r0 + a1.x * r1 + a2.x * r2 + a3.x * r3) * 0.25f + bv.x;
  o.y = (a0.y * r0 + a1.y * r1 + a2.y * r2 + a3.y * r3) * 0.25f + bv.y;
  if (fp16_relu) {
    o.x = fmaxf(o.x, 0.f); o.y = fmaxf(o.y, 0.f);
    ((__half2*)g_xh)[(size_t)w * 32 + lane] = __floats2half2_rn(o.x, o.y);
  } else {
    ((float2*)xout)[(size_t)w * 32 + lane] = o;
  }
}

// ---------------- per-node MLP heads ----------------
__global__ void k_heads(const float* __restrict__ emb,
                        const float* __restrict__ aw1, const float* __restrict__ ab1,
                        const float* __restrict__ aw2, const float* __restrict__ ab2,
                        const float* __restrict__ rw1, const float* __restrict__ rb1,
                        const float* __restrict__ rw2, const float* __restrict__ rb2,
                        const float* __restrict__ cw1, const float* __restrict__ cb1,
                        const float* __restrict__ cw2, const float* __restrict__ cb2,
                        float* __restrict__ anomaly, float* __restrict__ risk,
                        float* __restrict__ resource) {
  __shared__ float s_a1[2048], s_r1[2048], s_c1[2048];
  __shared__ float s_a2[32], s_r2[32], s_c2[160];
  __shared__ float s_ab1[32], s_rb1[32], s_cb1[32];
  __shared__ float s_ab2, s_rb2, s_cb2[5];
  int tid = threadIdx.x;
  for (int t = tid; t < 2048; t += blockDim.x) { s_a1[t] = aw1[t]; s_r1[t] = rw1[t]; s_c1[t] = cw1[t]; }
  for (int t = tid; t < 160; t += blockDim.x) s_c2[t] = cw2[t];
  if (tid < 32) { s_a2[tid] = aw2[tid]; s_r2[tid] = rw2[tid];
                  s_ab1[tid] = ab1[tid]; s_rb1[tid] = rb1[tid]; s_cb1[tid] = cb1[tid]; }
  if (tid == 0) { s_ab2 = ab2[0]; s_rb2 = rb2[0]; }
  if (tid < 5) s_cb2[tid] = cb2[tid];
  __syncthreads();
  int w = (blockIdx.x * blockDim.x + tid) >> 5;
  int lane = tid & 31;
  if (w >= NNODES) return;
  float e0 = emb[(size_t)w * 64 + lane];
  float e1 = emb[(size_t)w * 64 + 32 + lane];
  float ha = s_ab1[lane], hr = s_rb1[lane], hc = s_cb1[lane];
  #pragma unroll
  for (int c = 0; c < 32; c++) {
    float x = __shfl_sync(0xffffffffu, e0, c);
    ha = fmaf(x, s_a1[c * 32 + lane], ha);
    hr = fmaf(x, s_r1[c * 32 + lane], hr);
    hc = fmaf(x, s_c1[c * 32 + lane], hc);
  }
  #pragma unroll
  for (int c = 0; c < 32; c++) {
    float x = __shfl_sync(0xffffffffu, e1, c);
    ha = fmaf(x, s_a1[(c + 32) * 32 + lane], ha);
    hr = fmaf(x, s_r1[(c + 32) * 32 + lane], hr);
    hc = fmaf(x, s_c1[(c + 32) * 32 + lane], hc);
  }
  ha = fmaxf(ha, 0.f); hr = fmaxf(hr, 0.f); hc = fmaxf(hc, 0.f);
  float pa = warp_sum(ha * s_a2[lane]);
  float pr = warp_sum(hr * s_r2[lane]);
  if (lane == 0) {
    anomaly[w] = 1.f / (1.f + __expf(-(pa + s_ab2)));
    risk[w]    = 1.f / (1.f + __expf(-(pr + s_rb2)));
  }
  #pragma unroll
  for (int o = 0; o < 5; o++) {
    float p = warp_sum(hc * s_c2[lane * 5 + o]);
    if (lane == 0) resource[(size_t)w * 5 + o] = p + s_cb2[o];
  }
}

// ---------------- global mean pool + graph MLP ----------------
__global__ void k_pool(const float* __restrict__ emb, const int* __restrict__ batch,
                       const float* __restrict__ gw1, const float* __restrict__ gb1,
                       const float* __restrict__ gw2, const float* __restrict__ gb2,
                       float* __restrict__ glog) {
  __shared__ float part[256];
  __shared__ float pooled[64];
  __shared__ float hidden[32];
  __shared__ int s_lo, s_hi;
  int g = blockIdx.x;
  int tid = threadIdx.x;
  if (tid == 0) {
    int lo = 0, hi = NNODES;
    while (lo < hi) { int mid = (lo + hi) >> 1; if (batch[mid] < g) lo = mid + 1; else hi = mid; }
    int lo2 = lo, hi2 = NNODES;
    while (lo2 < hi2) { int mid = (lo2 + hi2) >> 1; if (batch[mid] <= g) lo2 = mid + 1; else hi2 = mid; }
    s_lo = lo; s_hi = lo2;
  }
  __syncthreads();
  int lo = s_lo, hi = s_hi;
  int c = tid & 63, sub = tid >> 6;
  float acc = 0.f;
  for (int i = lo + sub; i < hi; i += 4) acc += emb[(size_t)i * 64 + c];
  part[tid] = acc;
  __syncthreads();
  if (tid < 64) {
    float cnt = fmaxf((float)(hi - lo), 1.f);
    pooled[tid] = (part[tid] + part[tid + 64] + part[tid + 128] + part[tid + 192]) / cnt;
  }
  __syncthreads();
  if (tid < 32) {
    float h = gb1[tid];
    #pragma unroll
    for (int cc = 0; cc < 64; cc++) h = fmaf(pooled[cc], gw1[cc * 32 + tid], h);
    hidden[tid] = fmaxf(h, 0.f);
  }
  __syncthreads();
  if (tid < 4) {
    float o = gb2[tid];
    #pragma unroll
    for (int j = 0; j < 32; j++) o = fmaf(hidden[j], gw2[j * 4 + tid], o);
    glog[g * 4 + tid] = o;
  }
}

// ---------------- launch ----------------
extern "C" void kernel_launch(void* const* d_in, const int* in_sizes, int n_in,
                              void* d_out, int out_size) {
  const float* x     = (const float*)d_in[0];
  const int*   ei    = (const int*)d_in[1];
  const int*   batch = (const int*)d_in[2];
  const float* W1  = (const float*)d_in[3];
  const float* as1 = (const float*)d_in[4];
  const float* ad1 = (const float*)d_in[5];
  const float* b1  = (const float*)d_in[6];
  const float* W2  = (const float*)d_in[7];
  const float* as2 = (const float*)d_in[8];
  const float* ad2 = (const float*)d_in[9];
  const float* b2  = (const float*)d_in[10];
  const float* W3  = (const float*)d_in[11];
  const float* as3 = (const float*)d_in[12];
  const float* ad3 = (const float*)d_in[13];
  const float* b3  = (const float*)d_in[14];
  const float* aw1 = (const float*)d_in[15];
  const float* ab1 = (const float*)d_in[16];
  const float* aw2 = (const float*)d_in[17];
  const float* ab2 = (const float*)d_in[18];
  const float* rw1 = (const float*)d_in[19];
  const float* rb1 = (const float*)d_in[20];
  const float* rw2 = (const float*)d_in[21];
  const float* rb2 = (const float*)d_in[22];
  const float* cw1 = (const float*)d_in[23];
  const float* cb1 = (const float*)d_in[24];
  const float* cw2 = (const float*)d_in[25];
  const float* cb2 = (const float*)d_in[26];
  const float* gw1 = (const float*)d_in[27];
  const float* gb1 = (const float*)d_in[28];
  const float* gw2 = (const float*)d_in[29];
  const float* gb2 = (const float*)d_in[30];

  float* out      = (float*)d_out;
  float* emb      = out;                               // [N,64]
  float* anomaly  = emb + (size_t)NNODES * 64;         // [N]
  float* risk     = anomaly + NNODES;                  // [N]
  float* resource = risk + NNODES;                     // [N,5]
  float* glog     = resource + (size_t)NNODES * 5;     // [G,4]

  const int SMEM128 = 128 * 136 * 2 + 128 * 72 * 2 + 512;   // 53760
  const int SMEM64  = 128 * 72 * 2 + 64 * 72 * 2 + 512;     // 28160
  cudaFuncSetAttribute(k_gemm_mma<128>, cudaFuncAttributeMaxDynamicSharedMemorySize, SMEM128);
  cudaFuncSetAttribute(k_gemm_mma<64>,  cudaFuncAttributeMaxDynamicSharedMemorySize, SMEM64);

  // CSR build (dst-grouped, self-loops included)
  k_zero_counts<<<(NNODES + 255) / 256, 256>>>();
  k_count<<<(NETOT + 255) / 256, 256>>>(ei);
  k_scan1<<<NBLK_SCAN, 256>>>();
  k_scan2<<<1, 256>>>();
  k_scan3<<<(NNODES + 255) / 256, 256>>>();
  k_fill<<<(NETOT + 255) / 256, 256>>>(ei);
  k_xcast<<<(NNODES * 32 + 255) / 256, 256>>>(x);

  dim3 gemm_grid(4, (NNODES + 127) / 128);
  int warp_blocks = (NNODES * 32 + 255) / 256;
  int edge_blocks = (NETOT + 255) / 256;

  // Layer 1
  k_gemm_mma<128><<<gemm_grid, 256, SMEM128>>>(0, W1, as1, ad1);
  k_edgew<<<edge_blocks, 256>>>();
  k_aggregate<<<warp_blocks, 256>>>(b1, nullptr, 1);      // -> g_xh fp16 + relu
  // Layer 2
  k_gemm_mma<64><<<gemm_grid, 256, SMEM64>>>(1, W2, as2, ad2);
  k_edgew<<<edge_blocks, 256>>>();
  k_aggregate<<<warp_blocks, 256>>>(b2, nullptr, 1);      // -> g_xh fp16 + relu
  // Layer 3
  k_gemm_mma<64><<<gemm_grid, 256, SMEM64>>>(1, W3, as3, ad3);
  k_edgew<<<edge_blocks, 256>>>();
  k_aggregate<<<warp_blocks, 256>>>(b3, emb, 0);          // -> emb fp32, no relu

  // Heads + pooling
  k_heads<<<(NNODES * 32 + 511) / 512, 512>>>(emb, aw1, ab1, aw2, ab2,
                                              rw1, rb1, rw2, rb2,
                                              cw1, cb1, cw2, cb2,
                                              anomaly, risk, resource);
  k_pool<<<NGRAPH, 256>>>(emb, batch, gw1, gb1, gw2, gb2, glog);
}

// round 5
// speedup vs baseline: 3.3184x; 1.0235x over previous
#include <cuda_runtime.h>
#include <cuda_fp16.h>
#include <math.h>

#define NNODES 50000
#define NEDGES 800000
#define NETOT  (NEDGES + NNODES)
#define NGRAPH 64
#define NBLK_SCAN ((NNODES + 255) / 256)   // 196

// ---------------- scratch (device globals; no allocation allowed) ----------------
__device__ __half g_hh[NNODES * 256];    // projected features fp16; lane-interleaved:
                                         // row halves idx = 8*(c>>1) + 2*head + (c&1)
__device__ __half g_xh1[NNODES * 128];   // layer-1 input, fp16
__device__ __half g_xh[NNODES * 64];     // layer-2/3 input, fp16
__device__ float g_als[NNODES * 4];      // src attention logit per head
__device__ float g_ald[NNODES * 4];      // dst attention logit per head
__device__ float g_ew[NETOT * 4];        // per-edge unnormalized softmax weights
__device__ int   g_deg[NNODES];
__device__ int   g_rowptr[NNODES + 1];
__device__ int   g_cursor[NNODES];
__device__ int   g_bsum[256];
__device__ int2  g_edge[NETOT];          // (src, dst) per in-edge, grouped by dst

// ---------------- helpers ----------------
__device__ __forceinline__ float warp_sum(float v) {
  #pragma unroll
  for (int o = 16; o; o >>= 1) v += __shfl_xor_sync(0xffffffffu, v, o);
  return v;
}
__device__ __forceinline__ float lrelu(float v) { return v > 0.f ? v : 0.2f * v; }

typedef unsigned long long ull;
__device__ __forceinline__ ull pack2(float x, float y) {
  ull r; asm("mov.b64 %0,{%1,%2};" : "=l"(r) : "f"(x), "f"(y)); return r;
}
__device__ __forceinline__ void ffma2(ull& d, ull a, ull b) {
  asm("fma.rn.f32x2 %0,%1,%2,%0;" : "+l"(d) : "l"(a), "l"(b));
}
__device__ __forceinline__ void fadd2(ull& d, ull a) {
  asm("add.rn.f32x2 %0,%0,%1;" : "+l"(d) : "l"(a));
}
__device__ __forceinline__ float2 unpack2(ull v) {
  float2 f; asm("mov.b64 {%0,%1},%2;" : "=f"(f.x), "=f"(f.y) : "l"(v)); return f;
}

// ---------------- CSR build ----------------
__global__ void k_zero_counts() {
  int i = blockIdx.x * blockDim.x + threadIdx.x;
  if (i < NNODES) g_deg[i] = 0;
}

__global__ void k_count(const int* __restrict__ ei) {
  int i = blockIdx.x * blockDim.x + threadIdx.x;
  if (i >= NETOT) return;
  int d = (i < NEDGES) ? ei[NEDGES + i] : (i - NEDGES);   // self-loops appended
  atomicAdd(&g_deg[d], 1);
}

__global__ void k_scan1() {
  __shared__ int tmp[256];
  int tid = threadIdx.x;
  int i = blockIdx.x * 256 + tid;
  int v = (i < NNODES) ? g_deg[i] : 0;
  tmp[tid] = v;
  __syncthreads();
  #pragma unroll
  for (int d = 1; d < 256; d <<= 1) {
    int t = (tid >= d) ? tmp[tid - d] : 0;
    __syncthreads();
    tmp[tid] += t;
    __syncthreads();
  }
  if (i < NNODES) g_rowptr[i] = tmp[tid] - v;   // exclusive within block
  if (tid == 255) g_bsum[blockIdx.x] = tmp[255];
}

__global__ void k_scan2() {
  __shared__ int tmp[256];
  int tid = threadIdx.x;
  int v = (tid < NBLK_SCAN) ? g_bsum[tid] : 0;
  tmp[tid] = v;
  __syncthreads();
  #pragma unroll
  for (int d = 1; d < 256; d <<= 1) {
    int t = (tid >= d) ? tmp[tid - d] : 0;
    __syncthreads();
    tmp[tid] += t;
    __syncthreads();
  }
  g_bsum[tid] = tmp[tid] - v;
}

__global__ void k_scan3() {
  int i = blockIdx.x * blockDim.x + threadIdx.x;
  if (i < NNODES) {
    int v = g_rowptr[i] + g_bsum[i >> 8];
    g_rowptr[i] = v;
    g_cursor[i] = v;
  }
  if (i == 0) g_rowptr[NNODES] = NETOT;
}

__global__ void k_fill(const int* __restrict__ ei) {
  int i = blockIdx.x * blockDim.x + threadIdx.x;
  if (i >= NETOT) return;
  int s, d;
  if (i < NEDGES) { s = ei[i]; d = ei[NEDGES + i]; }
  else            { s = i - NEDGES; d = s; }
  int pos = atomicAdd(&g_cursor[d], 1);
  g_edge[pos] = make_int2(s, d);
}

// ---------------- layer-1 input cast fp32 -> fp16 ----------------
__global__ void k_xcast(const float* __restrict__ x) {
  int i = blockIdx.x * blockDim.x + threadIdx.x;   // float4 index
  if (i >= NNODES * 32) return;
  float4 v = ((const float4*)x)[i];
  __half2* o = (__half2*)g_xh1;
  o[i * 2]     = __floats2half2_rn(v.x, v.y);
  o[i * 2 + 1] = __floats2half2_rn(v.z, v.w);
}

// ---------------- edge-parallel softmax weights ----------------
__global__ void k_edgew() {
  int e = blockIdx.x * blockDim.x + threadIdx.x;
  if (e >= NETOT) return;
  int2 sd = g_edge[e];
  float4 as = ((const float4*)g_als)[sd.x];
  float4 ad = ((const float4*)g_ald)[sd.y];
  float4 w;
  w.x = __expf(lrelu(as.x + ad.x));
  w.y = __expf(lrelu(as.y + ad.y));
  w.z = __expf(lrelu(as.z + ad.z));
  w.w = __expf(lrelu(as.w + ad.w));
  ((float4*)g_ew)[e] = w;
}

// ---------------- tensor-core GEMM + logit epilogue ----------------
__device__ __forceinline__ void ldsm4(unsigned& r0, unsigned& r1, unsigned& r2, unsigned& r3,
                                      unsigned addr) {
  asm volatile("ldmatrix.sync.aligned.m8n8.x4.shared.b16 {%0,%1,%2,%3}, [%4];"
               : "=r"(r0), "=r"(r1), "=r"(r2), "=r"(r3) : "r"(addr));
}
__device__ __forceinline__ void ldsm2t(unsigned& r0, unsigned& r1, unsigned addr) {
  asm volatile("ldmatrix.sync.aligned.m8n8.x2.trans.shared.b16 {%0,%1}, [%2];"
               : "=r"(r0), "=r"(r1) : "r"(addr));
}
__device__ __forceinline__ void mma16816(float* c, const unsigned* a, const unsigned* b) {
  asm volatile("mma.sync.aligned.m16n8k16.row.col.f32.f16.f16.f32 "
               "{%0,%1,%2,%3},{%4,%5,%6,%7},{%8,%9},{%0,%1,%2,%3};"
               : "+f"(c[0]), "+f"(c[1]), "+f"(c[2]), "+f"(c[3])
               : "r"(a[0]), "r"(a[1]), "r"(a[2]), "r"(a[3]), "r"(b[0]), "r"(b[1]));
}

template<int K>
__global__ void __launch_bounds__(256) k_gemm_mma(
    int src_sel, const float* __restrict__ W,
    const float* __restrict__ a_s, const float* __restrict__ a_d) {
  constexpr int APAD = K + 8;
  constexpr int A_BYTES = 128 * APAD * 2;
  constexpr int B_BYTES = K * 72 * 2;
  extern __shared__ __align__(16) char dyn[];
  __half* As = (__half*)dyn;
  __half* Bs = (__half*)(dyn + A_BYTES);
  float* s_as = (float*)(dyn + A_BYTES + B_BYTES);
  float* s_ad = s_as + 64;
  float* red_s = (float*)dyn;                // overlay after mma: [128][2]
  float* red_d = (float*)(dyn + 1024);

  const __half* __restrict__ X = (src_sel == 0) ? g_xh1 : g_xh;
  int tid = threadIdx.x;
  int lane = tid & 31, wid = tid >> 5;
  int warp_m = wid >> 1, warp_n = wid & 1;
  int hd = blockIdx.x;
  int col0 = hd * 64;
  int row0 = blockIdx.y * 128;

  if (tid < 64) { s_as[tid] = a_s[col0 + tid]; s_ad[tid] = a_d[col0 + tid]; }

  constexpr int A_IT = 128 * K / 8 / 256;
  #pragma unroll
  for (int it = 0; it < A_IT; it++) {
    int idx = tid + it * 256;
    int r = idx / (K / 8), c8 = idx % (K / 8);
    uint4 v = make_uint4(0, 0, 0, 0);
    if (row0 + r < NNODES)
      v = *(const uint4*)&X[(size_t)(row0 + r) * K + c8 * 8];
    *(uint4*)&As[r * APAD + c8 * 8] = v;
  }
  constexpr int B_IT = K * 16 / 256;
  #pragma unroll
  for (int it = 0; it < B_IT; it++) {
    int idx = tid + it * 256;
    int k = idx >> 4, c4 = idx & 15;
    float4 v = *(const float4*)&W[(size_t)k * 256 + col0 + c4 * 4];
    __half2* o = (__half2*)&Bs[k * 72 + c4 * 4];
    o[0] = __floats2half2_rn(v.x, v.y);
    o[1] = __floats2half2_rn(v.z, v.w);
  }
  __syncthreads();

  unsigned As_u = (unsigned)__cvta_generic_to_shared(As);
  unsigned Bs_u = (unsigned)__cvta_generic_to_shared(Bs);
  unsigned a_base = As_u + ((warp_m * 32 + (lane & 15)) * APAD + (lane >> 4) * 8) * 2;
  unsigned b_base = Bs_u + ((lane & 15) * 72 + warp_n * 32) * 2;

  float acc[2][4][4];
  #pragma unroll
  for (int mt = 0; mt < 2; mt++)
    #pragma unroll
    for (int nt = 0; nt < 4; nt++)
      #pragma unroll
      for (int q = 0; q < 4; q++) acc[mt][nt][q] = 0.f;

  #pragma unroll
  for (int ks = 0; ks < K / 16; ks++) {
    unsigned a[2][4], b[4][2];
    #pragma unroll
    for (int mt = 0; mt < 2; mt++)
      ldsm4(a[mt][0], a[mt][1], a[mt][2], a[mt][3],
            a_base + (mt * 16 * APAD + ks * 16) * 2);
    #pragma unroll
    for (int nt = 0; nt < 4; nt++)
      ldsm2t(b[nt][0], b[nt][1], b_base + (ks * 16 * 72 + nt * 8) * 2);
    #pragma unroll
    for (int mt = 0; mt < 2; mt++)
      #pragma unroll
      for (int nt = 0; nt < 4; nt++)
        mma16816(acc[mt][nt], a[mt], b[nt]);
  }
  __syncthreads();   // reds overlay As

  int quad = lane >> 2, qid = lane & 3;
  #pragma unroll
  for (int mt = 0; mt < 2; mt++) {
    #pragma unroll
    for (int rh = 0; rh < 2; rh++) {
      int lr = warp_m * 32 + mt * 16 + rh * 8 + quad;
      int row = row0 + lr;
      float ss = 0.f, sd = 0.f;
      #pragma unroll
      for (int nt = 0; nt < 4; nt++) {
        float v0 = acc[mt][nt][rh * 2 + 0];
        float v1 = acc[mt][nt][rh * 2 + 1];
        int c = warp_n * 32 + nt * 8 + qid * 2;     // local even channel
        ss = fmaf(v0, s_as[c], fmaf(v1, s_as[c + 1], ss));
        sd = fmaf(v0, s_ad[c], fmaf(v1, s_ad[c + 1], sd));
        if (row < NNODES)   // lane-interleaved layout: 8*(c/2) + 2*hd
          *(__half2*)&g_hh[(size_t)row * 256 + c * 4 + hd * 2] = __floats2half2_rn(v0, v1);
      }
      ss += __shfl_xor_sync(0xffffffffu, ss, 1);
      ss += __shfl_xor_sync(0xffffffffu, ss, 2);
      sd += __shfl_xor_sync(0xffffffffu, sd, 1);
      sd += __shfl_xor_sync(0xffffffffu, sd, 2);
      if (qid == 0) { red_s[lr * 2 + warp_n] = ss; red_d[lr * 2 + warp_n] = sd; }
    }
  }
  __syncthreads();
  if (tid < 128) {
    int row = row0 + tid;
    if (row < NNODES) {
      g_als[row * 4 + hd] = red_s[tid * 2] + red_s[tid * 2 + 1];
      g_ald[row * 4 + hd] = red_d[tid * 2] + red_d[tid * 2 + 1];
    }
  }
}

// ---------------- GAT aggregate: weighted sum with precomputed edge weights ----------------
// one warp per dst node; lane l owns channels {2l, 2l+1} of all 4 heads ->
// one uint4 (16B) gather per lane = full 512B feature row per warp per edge.
// Edge loop unrolled x4 with front-batched gathers (explicit MLP=4).
__global__ void k_aggregate(const float* __restrict__ bias, float* __restrict__ xout,
                            int fp16_relu) {
  int w = (blockIdx.x * blockDim.x + threadIdx.x) >> 5;
  int lane = threadIdx.x & 31;
  if (w >= NNODES) return;
  int beg = g_rowptr[w], end = g_rowptr[w + 1];
  const uint4* __restrict__ H4 = (const uint4*)g_hh;     // 32 uint4 per row
  const float4* __restrict__ EW = (const float4*)g_ew;

  ull acc0 = 0, acc1 = 0, acc2 = 0, acc3 = 0;
  ull dd01 = 0, dd23 = 0;

#define EDGE_ACC(hv, wv)                                                  \
  do {                                                                    \
    fadd2(dd01, pack2((wv).x, (wv).y));                                   \
    fadd2(dd23, pack2((wv).z, (wv).w));                                   \
    float2 f0 = __half22float2(*(__half2*)&(hv).x);                       \
    float2 f1 = __half22float2(*(__half2*)&(hv).y);                       \
    float2 f2 = __half22float2(*(__half2*)&(hv).z);                       \
    float2 f3 = __half22float2(*(__half2*)&(hv).w);                       \
    ffma2(acc0, pack2(f0.x, f0.y), pack2((wv).x, (wv).x));                \
    ffma2(acc1, pack2(f1.x, f1.y), pack2((wv).y, (wv).y));                \
    ffma2(acc2, pack2(f2.x, f2.y), pack2((wv).z, (wv).z));                \
    ffma2(acc3, pack2(f3.x, f3.y), pack2((wv).w, (wv).w));                \
  } while (0)

  int e = beg;
  for (; e + 4 <= end; e += 4) {
    int s0 = g_edge[e].x;
    int s1 = g_edge[e + 1].x;
    int s2 = g_edge[e + 2].x;
    int s3 = g_edge[e + 3].x;
    float4 w0 = EW[e], w1 = EW[e + 1], w2 = EW[e + 2], w3 = EW[e + 3];
    uint4 h0 = H4[(size_t)s0 * 32 + lane];
    uint4 h1 = H4[(size_t)s1 * 32 + lane];
    uint4 h2 = H4[(size_t)s2 * 32 + lane];
    uint4 h3 = H4[(size_t)s3 * 32 + lane];
    EDGE_ACC(h0, w0);
    EDGE_ACC(h1, w1);
    EDGE_ACC(h2, w2);
    EDGE_ACC(h3, w3);
  }
  for (; e < end; e++) {
    int s = g_edge[e].x;
    float4 wv = EW[e];
    uint4 hv = H4[(size_t)s * 32 + lane];
    EDGE_ACC(hv, wv);
  }
#undef EDGE_ACC

  float2 d01 = unpack2(dd01), d23 = unpack2(dd23);
  float2 a0 = unpack2(acc0), a1 = unpack2(acc1), a2 = unpack2(acc2), a3 = unpack2(acc3);
  float r0 = 1.f / d01.x, r1 = 1.f / d01.y, r2 = 1.f / d23.x, r3 = 1.f / d23.y;
  float2 bv = ((const float2*)bias)[lane];
  float2 o;
  o.x = (a0.x * r0 + a1.x * r1 + a2.x * r2 + a3.x * r3) * 0.25f + bv.x;
  o.y = (a0.y * r0 + a1.y * r1 + a2.y * r2 + a3.y * r3) * 0.25f + bv.y;
  if (fp16_relu) {
    o.x = fmaxf(o.x, 0.f); o.y = fmaxf(o.y, 0.f);
    ((__half2*)g_xh)[(size_t)w * 32 + lane] = __floats2half2_rn(o.x, o.y);
  } else {
    ((float2*)xout)[(size_t)w * 32 + lane] = o;
  }
}

// ---------------- per-node MLP heads ----------------
__global__ void k_heads(const float* __restrict__ emb,
                        const float* __restrict__ aw1, const float* __restrict__ ab1,
                        const float* __restrict__ aw2, const float* __restrict__ ab2,
                        const float* __restrict__ rw1, const float* __restrict__ rb1,
                        const float* __restrict__ rw2, const float* __restrict__ rb2,
                        const float* __restrict__ cw1, const float* __restrict__ cb1,
                        const float* __restrict__ cw2, const float* __restrict__ cb2,
                        float* __restrict__ anomaly, float* __restrict__ risk,
                        float* __restrict__ resource) {
  __shared__ float s_a1[2048], s_r1[2048], s_c1[2048];
  __shared__ float s_a2[32], s_r2[32], s_c2[160];
  __shared__ float s_ab1[32], s_rb1[32], s_cb1[32];
  __shared__ float s_ab2, s_rb2, s_cb2[5];
  int tid = threadIdx.x;
  for (int t = tid; t < 2048; t += blockDim.x) { s_a1[t] = aw1[t]; s_r1[t] = rw1[t]; s_c1[t] = cw1[t]; }
  for (int t = tid; t < 160; t += blockDim.x) s_c2[t] = cw2[t];
  if (tid < 32) { s_a2[tid] = aw2[tid]; s_r2[tid] = rw2[tid];
                  s_ab1[tid] = ab1[tid]; s_rb1[tid] = rb1[tid]; s_cb1[tid] = cb1[tid]; }
  if (tid == 0) { s_ab2 = ab2[0]; s_rb2 = rb2[0]; }
  if (tid < 5) s_cb2[tid] = cb2[tid];
  __syncthreads();
  int w = (blockIdx.x * blockDim.x + tid) >> 5;
  int lane = tid & 31;
  if (w >= NNODES) return;
  float e0 = emb[(size_t)w * 64 + lane];
  float e1 = emb[(size_t)w * 64 + 32 + lane];
  float ha = s_ab1[lane], hr = s_rb1[lane], hc = s_cb1[lane];
  #pragma unroll
  for (int c = 0; c < 32; c++) {
    float x = __shfl_sync(0xffffffffu, e0, c);
    ha = fmaf(x, s_a1[c * 32 + lane], ha);
    hr = fmaf(x, s_r1[c * 32 + lane], hr);
    hc = fmaf(x, s_c1[c * 32 + lane], hc);
  }
  #pragma unroll
  for (int c = 0; c < 32; c++) {
    float x = __shfl_sync(0xffffffffu, e1, c);
    ha = fmaf(x, s_a1[(c + 32) * 32 + lane], ha);
    hr = fmaf(x, s_r1[(c + 32) * 32 + lane], hr);
    hc = fmaf(x, s_c1[(c + 32) * 32 + lane], hc);
  }
  ha = fmaxf(ha, 0.f); hr = fmaxf(hr, 0.f); hc = fmaxf(hc, 0.f);
  float pa = warp_sum(ha * s_a2[lane]);
  float pr = warp_sum(hr * s_r2[lane]);
  if (lane == 0) {
    anomaly[w] = 1.f / (1.f + __expf(-(pa + s_ab2)));
    risk[w]    = 1.f / (1.f + __expf(-(pr + s_rb2)));
  }
  #pragma unroll
  for (int o = 0; o < 5; o++) {
    float p = warp_sum(hc * s_c2[lane * 5 + o]);
    if (lane == 0) resource[(size_t)w * 5 + o] = p + s_cb2[o];
  }
}

// ---------------- global mean pool + graph MLP ----------------
__global__ void k_pool(const float* __restrict__ emb, const int* __restrict__ batch,
                       const float* __restrict__ gw1, const float* __restrict__ gb1,
                       const float* __restrict__ gw2, const float* __restrict__ gb2,
                       float* __restrict__ glog) {
  __shared__ float part[256];
  __shared__ float pooled[64];
  __shared__ float hidden[32];
  __shared__ int s_lo, s_hi;
  int g = blockIdx.x;
  int tid = threadIdx.x;
  if (tid == 0) {
    int lo = 0, hi = NNODES;
    while (lo < hi) { int mid = (lo + hi) >> 1; if (batch[mid] < g) lo = mid + 1; else hi = mid; }
    int lo2 = lo, hi2 = NNODES;
    while (lo2 < hi2) { int mid = (lo2 + hi2) >> 1; if (batch[mid] <= g) lo2 = mid + 1; else hi2 = mid; }
    s_lo = lo; s_hi = lo2;
  }
  __syncthreads();
  int lo = s_lo, hi = s_hi;
  int c = tid & 63, sub = tid >> 6;
  float acc = 0.f;
  for (int i = lo + sub; i < hi; i += 4) acc += emb[(size_t)i * 64 + c];
  part[tid] = acc;
  __syncthreads();
  if (tid < 64) {
    float cnt = fmaxf((float)(hi - lo), 1.f);
    pooled[tid] = (part[tid] + part[tid + 64] + part[tid + 128] + part[tid + 192]) / cnt;
  }
  __syncthreads();
  if (tid < 32) {
    float h = gb1[tid];
    #pragma unroll
    for (int cc = 0; cc < 64; cc++) h = fmaf(pooled[cc], gw1[cc * 32 + tid], h);
    hidden[tid] = fmaxf(h, 0.f);
  }
  __syncthreads();
  if (tid < 4) {
    float o = gb2[tid];
    #pragma unroll
    for (int j = 0; j < 32; j++) o = fmaf(hidden[j], gw2[j * 4 + tid], o);
    glog[g * 4 + tid] = o;
  }
}

// ---------------- launch ----------------
extern "C" void kernel_launch(void* const* d_in, const int* in_sizes, int n_in,
                              void* d_out, int out_size) {
  const float* x     = (const float*)d_in[0];
  const int*   ei    = (const int*)d_in[1];
  const int*   batch = (const int*)d_in[2];
  const float* W1  = (const float*)d_in[3];
  const float* as1 = (const float*)d_in[4];
  const float* ad1 = (const float*)d_in[5];
  const float* b1  = (const float*)d_in[6];
  const float* W2  = (const float*)d_in[7];
  const float* as2 = (const float*)d_in[8];
  const float* ad2 = (const float*)d_in[9];
  const float* b2  = (const float*)d_in[10];
  const float* W3  = (const float*)d_in[11];
  const float* as3 = (const float*)d_in[12];
  const float* ad3 = (const float*)d_in[13];
  const float* b3  = (const float*)d_in[14];
  const float* aw1 = (const float*)d_in[15];
  const float* ab1 = (const float*)d_in[16];
  const float* aw2 = (const float*)d_in[17];
  const float* ab2 = (const float*)d_in[18];
  const float* rw1 = (const float*)d_in[19];
  const float* rb1 = (const float*)d_in[20];
  const float* rw2 = (const float*)d_in[21];
  const float* rb2 = (const float*)d_in[22];
  const float* cw1 = (const float*)d_in[23];
  const float* cb1 = (const float*)d_in[24];
  const float* cw2 = (const float*)d_in[25];
  const float* cb2 = (const float*)d_in[26];
  const float* gw1 = (const float*)d_in[27];
  const float* gb1 = (const float*)d_in[28];
  const float* gw2 = (const float*)d_in[29];
  const float* gb2 = (const float*)d_in[30];

  float* out      = (float*)d_out;
  float* emb      = out;                               // [N,64]
  float* anomaly  = emb + (size_t)NNODES * 64;         // [N]
  float* risk     = anomaly + NNODES;                  // [N]
  float* resource = risk + NNODES;                     // [N,5]
  float* glog     = resource + (size_t)NNODES * 5;     // [G,4]

  const int SMEM128 = 128 * 136 * 2 + 128 * 72 * 2 + 512;   // 53760
  const int SMEM64  = 128 * 72 * 2 + 64 * 72 * 2 + 512;     // 28160
  cudaFuncSetAttribute(k_gemm_mma<128>, cudaFuncAttributeMaxDynamicSharedMemorySize, SMEM128);
  cudaFuncSetAttribute(k_gemm_mma<64>,  cudaFuncAttributeMaxDynamicSharedMemorySize, SMEM64);

  // CSR build (dst-grouped, self-loops included)
  k_zero_counts<<<(NNODES + 255) / 256, 256>>>();
  k_count<<<(NETOT + 255) / 256, 256>>>(ei);
  k_scan1<<<NBLK_SCAN, 256>>>();
  k_scan2<<<1, 256>>>();
  k_scan3<<<(NNODES + 255) / 256, 256>>>();
  k_fill<<<(NETOT + 255) / 256, 256>>>(ei);
  k_xcast<<<(NNODES * 32 + 255) / 256, 256>>>(x);

  dim3 gemm_grid(4, (NNODES + 127) / 128);
  int warp_blocks = (NNODES * 32 + 255) / 256;
  int edge_blocks = (NETOT + 255) / 256;

  // Layer 1
  k_gemm_mma<128><<<gemm_grid, 256, SMEM128>>>(0, W1, as1, ad1);
  k_edgew<<<edge_blocks, 256>>>();
  k_aggregate<<<warp_blocks, 256>>>(b1, nullptr, 1);      // -> g_xh fp16 + relu
  // Layer 2
  k_gemm_mma<64><<<gemm_grid, 256, SMEM64>>>(1, W2, as2, ad2);
  k_edgew<<<edge_blocks, 256>>>();
  k_aggregate<<<warp_blocks, 256>>>(b2, nullptr, 1);      // -> g_xh fp16 + relu
  // Layer 3
  k_gemm_mma<64><<<gemm_grid, 256, SMEM64>>>(1, W3, as3, ad3);
  k_edgew<<<edge_blocks, 256>>>();
  k_aggregate<<<warp_blocks, 256>>>(b3, emb, 0);          // -> emb fp32, no relu

  // Heads + pooling
  k_heads<<<(NNODES * 32 + 511) / 512, 512>>>(emb, aw1, ab1, aw2, ab2,
                                              rw1, rb1, rw2, rb2,
                                              cw1, cb1, cw2, cb2,
                                              anomaly, risk, resource);
  k_pool<<<NGRAPH, 256>>>(emb, batch, gw1, gb1, gw2, gb2, glog);
}